// round 2
// baseline (speedup 1.0000x reference)
#include <cuda_runtime.h>
#include <math.h>

// Problem constants (fixed by the dataset)
#define N_MAX 100000
#define E_MAX 3200000
#define FMAX  128

// ---------------- device scratch ----------------------------------------------
__device__ float g_dinv[N_MAX];
__device__ int   g_cnt[N_MAX];
__device__ int   g_rowstart[N_MAX];
__device__ int   g_cursor[N_MAX];
__device__ int2  g_sd[E_MAX];
__device__ int   g_csrc[E_MAX];
__device__ float g_tmp[(size_t)N_MAX * FMAX];
__device__ float g_h[(size_t)N_MAX * FMAX];
__device__ int   g_is64;

// ---------------- graph preprocessing ----------------------------------------

__global__ void k_zero_cnt(int n) {
    int i = blockIdx.x * blockDim.x + threadIdx.x;
    if (i < n) g_cnt[i] = 0;
}

// Detect whether the edge_index buffer is int64 or int32.
// int64 values < 2^31 have zero high words at all odd 32-bit positions;
// int32 data has random src indices there. 64 samples -> FP prob ~0.
__global__ void k_detect(const int* __restrict__ w) {
    int z = 0;
    #pragma unroll
    for (int i = 0; i < 64; i++) z |= w[2 * i + 1];
    g_is64 = (z == 0) ? 1 : 0;
}

// convert edge list -> int2, count in-degree (dtype-dispatched on device)
__global__ void k_prep(const void* __restrict__ ei, int e, int n) {
    int t = blockIdx.x * blockDim.x + threadIdx.x;
    if (t >= e) return;
    int s, d;
    if (g_is64) {
        const long long* p = (const long long*)ei;
        s = (int)p[t];
        d = (int)p[(size_t)e + t];
    } else {
        const int* p = (const int*)ei;
        s = p[t];
        d = p[e + t];
    }
    if ((unsigned)s >= (unsigned)n || (unsigned)d >= (unsigned)n) {
        g_sd[t] = make_int2(-1, -1);   // defensive: never crash on bad data
        return;
    }
    g_sd[t] = make_int2(s, d);
    atomicAdd(&g_cnt[d], 1);
}

__global__ void k_dinv(int n) {
    int i = blockIdx.x * blockDim.x + threadIdx.x;
    if (i < n) g_dinv[i] = rsqrtf((float)(g_cnt[i] + 1));  // +1 = self loop
}

// single-block exclusive scan of g_cnt -> g_rowstart, also init g_cursor
__global__ void k_scan(int n) {
    __shared__ int part[1024];
    int tid = threadIdx.x;
    int chunk = (n + 1023) >> 10;
    int b0 = tid * chunk;
    int b1 = b0 + chunk; if (b1 > n) b1 = n;
    int s = 0;
    for (int i = b0; i < b1; i++) s += g_cnt[i];
    part[tid] = s;
    __syncthreads();
    for (int off = 1; off < 1024; off <<= 1) {
        int t = (tid >= off) ? part[tid - off] : 0;
        __syncthreads();
        part[tid] += t;
        __syncthreads();
    }
    int run = part[tid] - s;  // exclusive prefix of this thread's chunk
    for (int i = b0; i < b1; i++) {
        g_rowstart[i] = run;
        g_cursor[i]   = run;
        run += g_cnt[i];
    }
}

// scatter sources into CSR-by-destination
__global__ void k_scatter(int e) {
    int t = blockIdx.x * blockDim.x + threadIdx.x;
    if (t >= e) return;
    int2 sd = g_sd[t];
    if (sd.y < 0) return;
    int pos = atomicAdd(&g_cursor[sd.y], 1);
    g_csrc[pos] = sd.x;
}

// ---------------- GEMM: out[row] = (A[row] @ W) * dinv[row] -------------------
template <int FIN, int FOUT>
__global__ void k_gemm(const float* __restrict__ A, const float* __restrict__ W,
                       float* __restrict__ out, int n) {
    constexpr int ROWS = 32;
    constexpr int G = 256 / FOUT;   // row groups per block
    constexpr int R = ROWS / G;     // rows per thread
    __shared__ float sA[ROWS * FIN];

    int row0 = blockIdx.x * ROWS;
    bool full = (row0 + ROWS) <= n;

    if (full) {
        const float4* src = (const float4*)(A + (size_t)row0 * FIN);
        float4* dstS = (float4*)sA;
        constexpr int T4 = ROWS * FIN / 4;
        #pragma unroll 4
        for (int i = threadIdx.x; i < T4; i += 256) dstS[i] = src[i];
    } else {
        for (int i = threadIdx.x; i < ROWS * FIN; i += 256) {
            int r = i / FIN, k = i - r * FIN;
            sA[i] = (row0 + r < n) ? A[(size_t)(row0 + r) * FIN + k] : 0.0f;
        }
    }
    __syncthreads();

    int c  = threadIdx.x % FOUT;
    int rg = threadIdx.x / FOUT;

    float acc[R];
    #pragma unroll
    for (int r = 0; r < R; r++) acc[r] = 0.0f;

    #pragma unroll 4
    for (int k = 0; k < FIN; k++) {
        float w = __ldg(&W[k * FOUT + c]);
        #pragma unroll
        for (int r = 0; r < R; r++)
            acc[r] = fmaf(sA[(rg + r * G) * FIN + k], w, acc[r]);
    }

    #pragma unroll
    for (int r = 0; r < R; r++) {
        int grow = row0 + rg + r * G;
        if (grow < n)
            out[(size_t)grow * FOUT + c] = acc[r] * g_dinv[grow];
    }
}

// Special GEMM for layer 5 (FIN=16, FOUT=2)
__global__ void k_gemm5(const float* __restrict__ A, const float* __restrict__ W,
                        float* __restrict__ out, int n) {
    __shared__ float sW[32];
    if (threadIdx.x < 32) sW[threadIdx.x] = W[threadIdx.x];
    __syncthreads();
    int row = blockIdx.x * blockDim.x + threadIdx.x;
    if (row >= n) return;
    const float4* a4 = (const float4*)(A + (size_t)row * 16);
    float acc0 = 0.0f, acc1 = 0.0f;
    #pragma unroll
    for (int q = 0; q < 4; q++) {
        float4 a = __ldg(&a4[q]);
        acc0 = fmaf(a.x, sW[(4*q+0)*2+0], acc0);
        acc1 = fmaf(a.x, sW[(4*q+0)*2+1], acc1);
        acc0 = fmaf(a.y, sW[(4*q+1)*2+0], acc0);
        acc1 = fmaf(a.y, sW[(4*q+1)*2+1], acc1);
        acc0 = fmaf(a.z, sW[(4*q+2)*2+0], acc0);
        acc1 = fmaf(a.z, sW[(4*q+2)*2+1], acc1);
        acc0 = fmaf(a.w, sW[(4*q+3)*2+0], acc0);
        acc1 = fmaf(a.w, sW[(4*q+3)*2+1], acc1);
    }
    float di = g_dinv[row];
    out[(size_t)row * 2 + 0] = acc0 * di;
    out[(size_t)row * 2 + 1] = acc1 * di;
}

// ---------------- aggregation: out[i] = relu?(b + dinv[i]*(tmp'[i] + sum_nbr tmp'[s]))
template <int FOUT, bool RELU>
__global__ void k_agg(const float* __restrict__ tmp, const float* __restrict__ bias,
                      float* __restrict__ out, int n) {
    constexpr int G = FOUT / 4;
    int t = blockIdx.x * blockDim.x + threadIdx.x;
    int node = t / G;
    int lane = t % G;
    if (node >= n) return;

    const float4* t4 = (const float4*)tmp;
    size_t base = (size_t)node * G + lane;
    float4 acc = __ldg(&t4[base]);  // self-loop term (tmp' already has dinv[src])

    int start = g_rowstart[node];
    int c = g_cnt[node];
    int j = 0;
    for (; j + 4 <= c; j += 4) {
        int s0 = __ldg(&g_csrc[start + j + 0]);
        int s1 = __ldg(&g_csrc[start + j + 1]);
        int s2 = __ldg(&g_csrc[start + j + 2]);
        int s3 = __ldg(&g_csrc[start + j + 3]);
        float4 v0 = __ldg(&t4[(size_t)s0 * G + lane]);
        float4 v1 = __ldg(&t4[(size_t)s1 * G + lane]);
        float4 v2 = __ldg(&t4[(size_t)s2 * G + lane]);
        float4 v3 = __ldg(&t4[(size_t)s3 * G + lane]);
        acc.x += (v0.x + v1.x) + (v2.x + v3.x);
        acc.y += (v0.y + v1.y) + (v2.y + v3.y);
        acc.z += (v0.z + v1.z) + (v2.z + v3.z);
        acc.w += (v0.w + v1.w) + (v2.w + v3.w);
    }
    for (; j < c; j++) {
        int s = __ldg(&g_csrc[start + j]);
        float4 v = __ldg(&t4[(size_t)s * G + lane]);
        acc.x += v.x; acc.y += v.y; acc.z += v.z; acc.w += v.w;
    }

    float di = g_dinv[node];
    float4 b = __ldg(&((const float4*)bias)[lane]);
    float4 r;
    r.x = fmaf(di, acc.x, b.x);
    r.y = fmaf(di, acc.y, b.y);
    r.z = fmaf(di, acc.z, b.z);
    r.w = fmaf(di, acc.w, b.w);
    if (RELU) {
        r.x = fmaxf(r.x, 0.0f); r.y = fmaxf(r.y, 0.0f);
        r.z = fmaxf(r.z, 0.0f); r.w = fmaxf(r.w, 0.0f);
    }
    ((float4*)out)[base] = r;
}

// Final layer: aggregate Fout=2 and fuse log_softmax, write directly to d_out
__global__ void k_agg_final(const float* __restrict__ tmp, const float* __restrict__ bias,
                            float* __restrict__ out, int n) {
    int node = blockIdx.x * blockDim.x + threadIdx.x;
    if (node >= n) return;
    const float2* t2 = (const float2*)tmp;
    float2 acc = __ldg(&t2[node]);  // self
    int start = g_rowstart[node];
    int c = g_cnt[node];
    int j = 0;
    for (; j + 4 <= c; j += 4) {
        int s0 = __ldg(&g_csrc[start + j + 0]);
        int s1 = __ldg(&g_csrc[start + j + 1]);
        int s2 = __ldg(&g_csrc[start + j + 2]);
        int s3 = __ldg(&g_csrc[start + j + 3]);
        float2 v0 = __ldg(&t2[s0]);
        float2 v1 = __ldg(&t2[s1]);
        float2 v2 = __ldg(&t2[s2]);
        float2 v3 = __ldg(&t2[s3]);
        acc.x += (v0.x + v1.x) + (v2.x + v3.x);
        acc.y += (v0.y + v1.y) + (v2.y + v3.y);
    }
    for (; j < c; j++) {
        float2 v = __ldg(&t2[__ldg(&g_csrc[start + j])]);
        acc.x += v.x; acc.y += v.y;
    }
    float di = g_dinv[node];
    float z0 = fmaf(di, acc.x, bias[0]);
    float z1 = fmaf(di, acc.y, bias[1]);
    float m = fmaxf(z0, z1);
    float l = m + logf(expf(z0 - m) + expf(z1 - m));
    out[(size_t)node * 2 + 0] = z0 - l;
    out[(size_t)node * 2 + 1] = z1 - l;
}

// ---------------- launch -------------------------------------------------------
extern "C" void kernel_launch(void* const* d_in, const int* in_sizes, int n_in,
                              void* d_out, int out_size) {
    const float* x  = (const float*)d_in[0];
    const void*  ei = d_in[1];
    const float* W1 = (const float*)d_in[2];  const float* b1 = (const float*)d_in[3];
    const float* W2 = (const float*)d_in[4];  const float* b2 = (const float*)d_in[5];
    const float* W3 = (const float*)d_in[6];  const float* b3 = (const float*)d_in[7];
    const float* W4 = (const float*)d_in[8];  const float* b4 = (const float*)d_in[9];
    const float* W5 = (const float*)d_in[10]; const float* b5 = (const float*)d_in[11];

    int n = in_sizes[0] / 256;  // 100000
    int e = in_sizes[1] / 2;    // 3200000

    float* tmp_p = nullptr;
    float* h_p   = nullptr;
    cudaGetSymbolAddress((void**)&tmp_p, g_tmp);
    cudaGetSymbolAddress((void**)&h_p,   g_h);

    int nb_n = (n + 255) / 256;
    int nb_e = (e + 255) / 256;

    // graph preprocessing (recomputed every call — deterministic work)
    k_detect<<<1, 1>>>((const int*)ei);
    k_zero_cnt<<<nb_n, 256>>>(n);
    k_prep<<<nb_e, 256>>>(ei, e, n);
    k_dinv<<<nb_n, 256>>>(n);
    k_scan<<<1, 1024>>>(n);
    k_scatter<<<nb_e, 256>>>(e);

    int gemm_blocks = (n + 31) / 32;

    // Layer 1: 256 -> 64
    k_gemm<256, 64><<<gemm_blocks, 256>>>(x, W1, tmp_p, n);
    k_agg<64, true><<<((size_t)n * 16 + 255) / 256, 256>>>(tmp_p, b1, h_p, n);
    // Layer 2: 64 -> 128
    k_gemm<64, 128><<<gemm_blocks, 256>>>(h_p, W2, tmp_p, n);
    k_agg<128, true><<<((size_t)n * 32 + 255) / 256, 256>>>(tmp_p, b2, h_p, n);
    // Layer 3: 128 -> 64
    k_gemm<128, 64><<<gemm_blocks, 256>>>(h_p, W3, tmp_p, n);
    k_agg<64, true><<<((size_t)n * 16 + 255) / 256, 256>>>(tmp_p, b3, h_p, n);
    // Layer 4: 64 -> 16
    k_gemm<64, 16><<<gemm_blocks, 256>>>(h_p, W4, tmp_p, n);
    k_agg<16, true><<<((size_t)n * 4 + 255) / 256, 256>>>(tmp_p, b4, h_p, n);
    // Layer 5: 16 -> 2, fused log_softmax
    k_gemm5<<<nb_n, 256>>>(h_p, W5, tmp_p, n);
    k_agg_final<<<nb_n, 256>>>(tmp_p, b5, (float*)d_out, n);
}

// round 3
// speedup vs baseline: 1.2801x; 1.2801x over previous
#include <cuda_runtime.h>
#include <math.h>

// Problem constants (fixed by the dataset)
#define N_MAX 100000
#define E_MAX 3200000
#define FMAX  128

// ---------------- device scratch ----------------------------------------------
__device__ float g_dinv[N_MAX];
__device__ int   g_cnt[N_MAX];
__device__ int   g_rowstart[N_MAX];
__device__ int   g_cursor[N_MAX];
__device__ int   g_csrc[E_MAX];
__device__ float g_tmp[(size_t)N_MAX * FMAX];
__device__ float g_h[(size_t)N_MAX * FMAX];
__device__ int   g_is64;
__device__ int   g_bsum[512];
__device__ int   g_boff[512];

// ---------------- graph preprocessing ----------------------------------------

__global__ void k_zero_cnt(int n) {
    int i = blockIdx.x * blockDim.x + threadIdx.x;
    if (i < n) g_cnt[i] = 0;
}

// Detect int64 vs int32 edge buffer: int64 values < 2^31 have zero odd words.
__global__ void k_detect(const int* __restrict__ w) {
    int z = 0;
    #pragma unroll
    for (int i = 0; i < 64; i++) z |= w[2 * i + 1];
    g_is64 = (z == 0) ? 1 : 0;
}

// count in-degree, reading dst directly from the edge buffer
__global__ void k_count(const void* __restrict__ ei, int e, int n) {
    int t = blockIdx.x * blockDim.x + threadIdx.x;
    if (t >= e) return;
    int d;
    if (g_is64) d = (int)((const long long*)ei)[(size_t)e + t];
    else        d = ((const int*)ei)[e + t];
    if ((unsigned)d < (unsigned)n) atomicAdd(&g_cnt[d], 1);
}

// per-block sums of g_cnt
__global__ void k_bsum(int n) {
    int i = blockIdx.x * 256 + threadIdx.x;
    int v = (i < n) ? g_cnt[i] : 0;
    #pragma unroll
    for (int o = 16; o; o >>= 1) v += __shfl_down_sync(0xFFFFFFFFu, v, o);
    __shared__ int ws[8];
    if ((threadIdx.x & 31) == 0) ws[threadIdx.x >> 5] = v;
    __syncthreads();
    if (threadIdx.x == 0) {
        int s = 0;
        #pragma unroll
        for (int j = 0; j < 8; j++) s += ws[j];
        g_bsum[blockIdx.x] = s;
    }
}

// single-block exclusive scan of block sums (nb <= 512)
__global__ void k_bscan(int nb) {
    __shared__ int sm[512];
    int t = threadIdx.x;
    int v = (t < nb) ? g_bsum[t] : 0;
    sm[t] = v;
    __syncthreads();
    for (int o = 1; o < 512; o <<= 1) {
        int y = (t >= o) ? sm[t - o] : 0;
        __syncthreads();
        sm[t] += y;
        __syncthreads();
    }
    if (t < nb) g_boff[t] = sm[t] - v;
}

// per-block exclusive scan + rowstart/cursor/dinv in one pass
__global__ void k_final(int n) {
    int i = blockIdx.x * 256 + threadIdx.x;
    int v = (i < n) ? g_cnt[i] : 0;
    int lane = threadIdx.x & 31, wid = threadIdx.x >> 5;
    int x = v;
    #pragma unroll
    for (int o = 1; o < 32; o <<= 1) {
        int y = __shfl_up_sync(0xFFFFFFFFu, x, o);
        if (lane >= o) x += y;
    }
    __shared__ int ws[8];
    if (lane == 31) ws[wid] = x;
    __syncthreads();
    if (threadIdx.x < 8) {
        int y = ws[threadIdx.x];
        int z = y;
        #pragma unroll
        for (int o = 1; o < 8; o <<= 1) {
            int t2 = __shfl_up_sync(0xFFu, z, o);
            if (threadIdx.x >= o) z += t2;
        }
        ws[threadIdx.x] = z - y;  // exclusive warp offset
    }
    __syncthreads();
    if (i < n) {
        int excl = (x - v) + ws[wid] + g_boff[blockIdx.x];
        g_rowstart[i] = excl;
        g_cursor[i]   = excl;
        g_dinv[i]     = rsqrtf((float)(v + 1));  // +1 = self loop
    }
}

// scatter sources into CSR-by-destination (reads edge buffer directly)
__global__ void k_scatter(const void* __restrict__ ei, int e, int n) {
    int t = blockIdx.x * blockDim.x + threadIdx.x;
    if (t >= e) return;
    int s, d;
    if (g_is64) {
        const long long* p = (const long long*)ei;
        s = (int)p[t];
        d = (int)p[(size_t)e + t];
    } else {
        const int* p = (const int*)ei;
        s = p[t];
        d = p[e + t];
    }
    if ((unsigned)s >= (unsigned)n || (unsigned)d >= (unsigned)n) return;
    int pos = atomicAdd(&g_cursor[d], 1);
    g_csrc[pos] = s;
}

// ---------------- GEMM: out[row] = (A[row] @ W) * dinv[row] -------------------
// Pair-interleaved smem tile + packed fma.rn.f32x2 (2 rows per FMA instruction).
// Layout: pair p (rows 2p,2p+1) at sP[p*STRIDE + 2k + parity]; STRIDE = 2*FIN+2
// keeps writer banks conflict-free (2p+parity distinct mod 32) and 8B alignment.
template <int FIN, int FOUT>
__global__ void k_gemm(const float* __restrict__ A, const float* __restrict__ W,
                       float* __restrict__ out, int n) {
    constexpr int ROWS = 32;
    constexpr int G = 256 / FOUT;   // row groups per block
    constexpr int R = ROWS / G;     // rows per thread (even)
    constexpr int P = R / 2;        // row pairs per thread
    constexpr int STRIDE = 2 * FIN + 2;
    __shared__ __align__(16) float sP[(ROWS / 2) * STRIDE];

    int row0 = blockIdx.x * ROWS;

    // writer: lane = row, warp strides over k4 chunks
    {
        int lane = threadIdx.x & 31, w = threadIdx.x >> 5;
        int grow = row0 + lane;
        float* dst = &sP[(lane >> 1) * STRIDE + (lane & 1)];
        const float4* src = (const float4*)(A + (size_t)grow * FIN);
        for (int k4 = w; k4 < FIN / 4; k4 += 8) {
            float4 a = (grow < n) ? __ldg(&src[k4]) : make_float4(0.f, 0.f, 0.f, 0.f);
            dst[2 * (4 * k4 + 0)] = a.x;
            dst[2 * (4 * k4 + 1)] = a.y;
            dst[2 * (4 * k4 + 2)] = a.z;
            dst[2 * (4 * k4 + 3)] = a.w;
        }
    }
    __syncthreads();

    int c  = threadIdx.x % FOUT;
    int rg = threadIdx.x / FOUT;

    unsigned long long acc[P];
    #pragma unroll
    for (int q = 0; q < P; q++) acc[q] = 0ULL;

    const float* base = &sP[(rg * P) * STRIDE];

    #pragma unroll 4
    for (int k = 0; k < FIN; k++) {
        float w = __ldg(&W[k * FOUT + c]);
        unsigned long long w2;
        asm("mov.b64 %0, {%1, %1};" : "=l"(w2) : "f"(w));
        #pragma unroll
        for (int q = 0; q < P; q++) {
            unsigned long long a = *(const unsigned long long*)&base[q * STRIDE + 2 * k];
            asm("fma.rn.f32x2 %0, %1, %2, %0;" : "+l"(acc[q]) : "l"(a), "l"(w2));
        }
    }

    #pragma unroll
    for (int q = 0; q < P; q++) {
        float lo, hi;
        asm("mov.b64 {%0, %1}, %2;" : "=f"(lo), "=f"(hi) : "l"(acc[q]));
        int r0 = row0 + rg * R + 2 * q;
        if (r0 < n)     out[(size_t)r0 * FOUT + c]       = lo * g_dinv[r0];
        if (r0 + 1 < n) out[(size_t)(r0 + 1) * FOUT + c] = hi * g_dinv[r0 + 1];
    }
}

// Special GEMM for layer 5 (FIN=16, FOUT=2)
__global__ void k_gemm5(const float* __restrict__ A, const float* __restrict__ W,
                        float* __restrict__ out, int n) {
    __shared__ float sW[32];
    if (threadIdx.x < 32) sW[threadIdx.x] = W[threadIdx.x];
    __syncthreads();
    int row = blockIdx.x * blockDim.x + threadIdx.x;
    if (row >= n) return;
    const float4* a4 = (const float4*)(A + (size_t)row * 16);
    float acc0 = 0.0f, acc1 = 0.0f;
    #pragma unroll
    for (int q = 0; q < 4; q++) {
        float4 a = __ldg(&a4[q]);
        acc0 = fmaf(a.x, sW[(4*q+0)*2+0], acc0);
        acc1 = fmaf(a.x, sW[(4*q+0)*2+1], acc1);
        acc0 = fmaf(a.y, sW[(4*q+1)*2+0], acc0);
        acc1 = fmaf(a.y, sW[(4*q+1)*2+1], acc1);
        acc0 = fmaf(a.z, sW[(4*q+2)*2+0], acc0);
        acc1 = fmaf(a.z, sW[(4*q+2)*2+1], acc1);
        acc0 = fmaf(a.w, sW[(4*q+3)*2+0], acc0);
        acc1 = fmaf(a.w, sW[(4*q+3)*2+1], acc1);
    }
    float di = g_dinv[row];
    out[(size_t)row * 2 + 0] = acc0 * di;
    out[(size_t)row * 2 + 1] = acc1 * di;
}

// ---------------- aggregation: out[i] = relu?(b + dinv[i]*(tmp'[i] + sum_nbr tmp'[s]))
template <int FOUT, bool RELU>
__global__ void k_agg(const float* __restrict__ tmp, const float* __restrict__ bias,
                      float* __restrict__ out, int n) {
    constexpr int G = FOUT / 4;
    int t = blockIdx.x * blockDim.x + threadIdx.x;
    int node = t / G;
    int lane = t % G;
    if (node >= n) return;

    const float4* t4 = (const float4*)tmp;
    size_t base = (size_t)node * G + lane;
    float4 acc = __ldg(&t4[base]);  // self-loop term (tmp' already has dinv[src])

    int start = g_rowstart[node];
    int c = g_cnt[node];
    int j = 0;
    for (; j + 4 <= c; j += 4) {
        int s0 = __ldg(&g_csrc[start + j + 0]);
        int s1 = __ldg(&g_csrc[start + j + 1]);
        int s2 = __ldg(&g_csrc[start + j + 2]);
        int s3 = __ldg(&g_csrc[start + j + 3]);
        float4 v0 = __ldg(&t4[(size_t)s0 * G + lane]);
        float4 v1 = __ldg(&t4[(size_t)s1 * G + lane]);
        float4 v2 = __ldg(&t4[(size_t)s2 * G + lane]);
        float4 v3 = __ldg(&t4[(size_t)s3 * G + lane]);
        acc.x += (v0.x + v1.x) + (v2.x + v3.x);
        acc.y += (v0.y + v1.y) + (v2.y + v3.y);
        acc.z += (v0.z + v1.z) + (v2.z + v3.z);
        acc.w += (v0.w + v1.w) + (v2.w + v3.w);
    }
    for (; j < c; j++) {
        int s = __ldg(&g_csrc[start + j]);
        float4 v = __ldg(&t4[(size_t)s * G + lane]);
        acc.x += v.x; acc.y += v.y; acc.z += v.z; acc.w += v.w;
    }

    float di = g_dinv[node];
    float4 b = __ldg(&((const float4*)bias)[lane]);
    float4 r;
    r.x = fmaf(di, acc.x, b.x);
    r.y = fmaf(di, acc.y, b.y);
    r.z = fmaf(di, acc.z, b.z);
    r.w = fmaf(di, acc.w, b.w);
    if (RELU) {
        r.x = fmaxf(r.x, 0.0f); r.y = fmaxf(r.y, 0.0f);
        r.z = fmaxf(r.z, 0.0f); r.w = fmaxf(r.w, 0.0f);
    }
    ((float4*)out)[base] = r;
}

// Final layer: aggregate Fout=2 and fuse log_softmax, write directly to d_out
__global__ void k_agg_final(const float* __restrict__ tmp, const float* __restrict__ bias,
                            float* __restrict__ out, int n) {
    int node = blockIdx.x * blockDim.x + threadIdx.x;
    if (node >= n) return;
    const float2* t2 = (const float2*)tmp;
    float2 acc = __ldg(&t2[node]);  // self
    int start = g_rowstart[node];
    int c = g_cnt[node];
    int j = 0;
    for (; j + 4 <= c; j += 4) {
        int s0 = __ldg(&g_csrc[start + j + 0]);
        int s1 = __ldg(&g_csrc[start + j + 1]);
        int s2 = __ldg(&g_csrc[start + j + 2]);
        int s3 = __ldg(&g_csrc[start + j + 3]);
        float2 v0 = __ldg(&t2[s0]);
        float2 v1 = __ldg(&t2[s1]);
        float2 v2 = __ldg(&t2[s2]);
        float2 v3 = __ldg(&t2[s3]);
        acc.x += (v0.x + v1.x) + (v2.x + v3.x);
        acc.y += (v0.y + v1.y) + (v2.y + v3.y);
    }
    for (; j < c; j++) {
        float2 v = __ldg(&t2[__ldg(&g_csrc[start + j])]);
        acc.x += v.x; acc.y += v.y;
    }
    float di = g_dinv[node];
    float z0 = fmaf(di, acc.x, bias[0]);
    float z1 = fmaf(di, acc.y, bias[1]);
    float m = fmaxf(z0, z1);
    float l = m + logf(expf(z0 - m) + expf(z1 - m));
    out[(size_t)node * 2 + 0] = z0 - l;
    out[(size_t)node * 2 + 1] = z1 - l;
}

// ---------------- launch -------------------------------------------------------
extern "C" void kernel_launch(void* const* d_in, const int* in_sizes, int n_in,
                              void* d_out, int out_size) {
    const float* x  = (const float*)d_in[0];
    const void*  ei = d_in[1];
    const float* W1 = (const float*)d_in[2];  const float* b1 = (const float*)d_in[3];
    const float* W2 = (const float*)d_in[4];  const float* b2 = (const float*)d_in[5];
    const float* W3 = (const float*)d_in[6];  const float* b3 = (const float*)d_in[7];
    const float* W4 = (const float*)d_in[8];  const float* b4 = (const float*)d_in[9];
    const float* W5 = (const float*)d_in[10]; const float* b5 = (const float*)d_in[11];

    int n = in_sizes[0] / 256;  // 100000
    int e = in_sizes[1] / 2;    // 3200000

    float* tmp_p = nullptr;
    float* h_p   = nullptr;
    cudaGetSymbolAddress((void**)&tmp_p, g_tmp);
    cudaGetSymbolAddress((void**)&h_p,   g_h);

    int nb_n = (n + 255) / 256;   // 391
    int nb_e = (e + 255) / 256;

    // graph preprocessing (recomputed every call — deterministic work)
    k_detect<<<1, 1>>>((const int*)ei);
    k_zero_cnt<<<nb_n, 256>>>(n);
    k_count<<<nb_e, 256>>>(ei, e, n);
    k_bsum<<<nb_n, 256>>>(n);
    k_bscan<<<1, 512>>>(nb_n);
    k_final<<<nb_n, 256>>>(n);
    k_scatter<<<nb_e, 256>>>(ei, e, n);

    int gemm_blocks = (n + 31) / 32;

    // Layer 1: 256 -> 64
    k_gemm<256, 64><<<gemm_blocks, 256>>>(x, W1, tmp_p, n);
    k_agg<64, true><<<((size_t)n * 16 + 255) / 256, 256>>>(tmp_p, b1, h_p, n);
    // Layer 2: 64 -> 128
    k_gemm<64, 128><<<gemm_blocks, 256>>>(h_p, W2, tmp_p, n);
    k_agg<128, true><<<((size_t)n * 32 + 255) / 256, 256>>>(tmp_p, b2, h_p, n);
    // Layer 3: 128 -> 64
    k_gemm<128, 64><<<gemm_blocks, 256>>>(h_p, W3, tmp_p, n);
    k_agg<64, true><<<((size_t)n * 16 + 255) / 256, 256>>>(tmp_p, b3, h_p, n);
    // Layer 4: 64 -> 16
    k_gemm<64, 16><<<gemm_blocks, 256>>>(h_p, W4, tmp_p, n);
    k_agg<16, true><<<((size_t)n * 4 + 255) / 256, 256>>>(tmp_p, b4, h_p, n);
    // Layer 5: 16 -> 2, fused log_softmax
    k_gemm5<<<nb_n, 256>>>(h_p, W5, tmp_p, n);
    k_agg_final<<<nb_n, 256>>>(tmp_p, b5, (float*)d_out, n);
}

// round 4
// speedup vs baseline: 1.3753x; 1.0744x over previous
#include <cuda_runtime.h>
#include <math.h>

// Problem constants (fixed by the dataset)
#define N_MAX 100000
#define E_MAX 3200000
#define FMAX  128

// ---------------- device scratch ----------------------------------------------
__device__ float g_dinv[N_MAX];
__device__ int   g_cnt[N_MAX];
__device__ int   g_rowstart[N_MAX];
__device__ int   g_cursor[N_MAX];
__device__ int   g_csrc[E_MAX];
__device__ float g_tmp[(size_t)N_MAX * FMAX];
__device__ float g_h[(size_t)N_MAX * FMAX];
__device__ int   g_is64;
__device__ int   g_bsum[512];
__device__ int   g_boff[512];

// Epilogue modes
#define EPI_DINV      0   // out = acc * dinv[row]              (transform-first)
#define EPI_BIAS_RELU 1   // out = relu(acc + bias[c])          (aggregate-first)

#define AGG_RELU      0   // out = relu(b + dinv*sum)
#define AGG_RELU_DINV 1   // out = relu(b + dinv*sum) * dinv    (pre-scaled for next agg)
#define AGG_PRE       2   // out = dinv*sum                     (no bias/relu)

// ---------------- graph preprocessing ----------------------------------------

__global__ void k_zero_cnt(int n) {
    int i = blockIdx.x * blockDim.x + threadIdx.x;
    if (i < n) g_cnt[i] = 0;
}

// Detect int64 vs int32 edge buffer: int64 values < 2^31 have zero odd words.
__global__ void k_detect(const int* __restrict__ w) {
    int z = 0;
    #pragma unroll
    for (int i = 0; i < 64; i++) z |= w[2 * i + 1];
    g_is64 = (z == 0) ? 1 : 0;
}

// count in-degree, reading dst directly from the edge buffer
__global__ void k_count(const void* __restrict__ ei, int e, int n) {
    int t = blockIdx.x * blockDim.x + threadIdx.x;
    if (t >= e) return;
    int d;
    if (g_is64) d = (int)((const long long*)ei)[(size_t)e + t];
    else        d = ((const int*)ei)[e + t];
    if ((unsigned)d < (unsigned)n) atomicAdd(&g_cnt[d], 1);
}

// per-block sums of g_cnt
__global__ void k_bsum(int n) {
    int i = blockIdx.x * 256 + threadIdx.x;
    int v = (i < n) ? g_cnt[i] : 0;
    #pragma unroll
    for (int o = 16; o; o >>= 1) v += __shfl_down_sync(0xFFFFFFFFu, v, o);
    __shared__ int ws[8];
    if ((threadIdx.x & 31) == 0) ws[threadIdx.x >> 5] = v;
    __syncthreads();
    if (threadIdx.x == 0) {
        int s = 0;
        #pragma unroll
        for (int j = 0; j < 8; j++) s += ws[j];
        g_bsum[blockIdx.x] = s;
    }
}

// single-block exclusive scan of block sums (nb <= 512)
__global__ void k_bscan(int nb) {
    __shared__ int sm[512];
    int t = threadIdx.x;
    int v = (t < nb) ? g_bsum[t] : 0;
    sm[t] = v;
    __syncthreads();
    for (int o = 1; o < 512; o <<= 1) {
        int y = (t >= o) ? sm[t - o] : 0;
        __syncthreads();
        sm[t] += y;
        __syncthreads();
    }
    if (t < nb) g_boff[t] = sm[t] - v;
}

// per-block exclusive scan + rowstart/cursor/dinv in one pass
__global__ void k_final(int n) {
    int i = blockIdx.x * 256 + threadIdx.x;
    int v = (i < n) ? g_cnt[i] : 0;
    int lane = threadIdx.x & 31, wid = threadIdx.x >> 5;
    int x = v;
    #pragma unroll
    for (int o = 1; o < 32; o <<= 1) {
        int y = __shfl_up_sync(0xFFFFFFFFu, x, o);
        if (lane >= o) x += y;
    }
    __shared__ int ws[8];
    if (lane == 31) ws[wid] = x;
    __syncthreads();
    if (threadIdx.x < 8) {
        int y = ws[threadIdx.x];
        int z = y;
        #pragma unroll
        for (int o = 1; o < 8; o <<= 1) {
            int t2 = __shfl_up_sync(0xFFu, z, o);
            if (threadIdx.x >= o) z += t2;
        }
        ws[threadIdx.x] = z - y;  // exclusive warp offset
    }
    __syncthreads();
    if (i < n) {
        int excl = (x - v) + ws[wid] + g_boff[blockIdx.x];
        g_rowstart[i] = excl;
        g_cursor[i]   = excl;
        g_dinv[i]     = rsqrtf((float)(v + 1));  // +1 = self loop
    }
}

// scatter sources into CSR-by-destination (reads edge buffer directly)
__global__ void k_scatter(const void* __restrict__ ei, int e, int n) {
    int t = blockIdx.x * blockDim.x + threadIdx.x;
    if (t >= e) return;
    int s, d;
    if (g_is64) {
        const long long* p = (const long long*)ei;
        s = (int)p[t];
        d = (int)p[(size_t)e + t];
    } else {
        const int* p = (const int*)ei;
        s = p[t];
        d = p[e + t];
    }
    if ((unsigned)s >= (unsigned)n || (unsigned)d >= (unsigned)n) return;
    int pos = atomicAdd(&g_cursor[d], 1);
    g_csrc[pos] = s;
}

// ---------------- GEMM with selectable epilogue -------------------------------
// Pair-interleaved smem tile + packed fma.rn.f32x2 (2 rows per FMA instruction).
template <int FIN, int FOUT, int EPI>
__global__ void k_gemm(const float* __restrict__ A, const float* __restrict__ W,
                       float* __restrict__ out, const float* __restrict__ bias, int n) {
    constexpr int ROWS = 32;
    constexpr int G = 256 / FOUT;   // row groups per block
    constexpr int R = ROWS / G;     // rows per thread (even)
    constexpr int P = R / 2;        // row pairs per thread
    constexpr int STRIDE = 2 * FIN + 2;
    __shared__ __align__(16) float sP[(ROWS / 2) * STRIDE];

    int row0 = blockIdx.x * ROWS;

    // writer: lane = row, warp strides over k4 chunks
    {
        int lane = threadIdx.x & 31, w = threadIdx.x >> 5;
        int grow = row0 + lane;
        float* dst = &sP[(lane >> 1) * STRIDE + (lane & 1)];
        const float4* src = (const float4*)(A + (size_t)grow * FIN);
        for (int k4 = w; k4 < FIN / 4; k4 += 8) {
            float4 a = (grow < n) ? __ldg(&src[k4]) : make_float4(0.f, 0.f, 0.f, 0.f);
            dst[2 * (4 * k4 + 0)] = a.x;
            dst[2 * (4 * k4 + 1)] = a.y;
            dst[2 * (4 * k4 + 2)] = a.z;
            dst[2 * (4 * k4 + 3)] = a.w;
        }
    }
    __syncthreads();

    int c  = threadIdx.x % FOUT;
    int rg = threadIdx.x / FOUT;

    unsigned long long acc[P];
    #pragma unroll
    for (int q = 0; q < P; q++) acc[q] = 0ULL;

    const float* base = &sP[(rg * P) * STRIDE];

    #pragma unroll 4
    for (int k = 0; k < FIN; k++) {
        float w = __ldg(&W[k * FOUT + c]);
        unsigned long long w2;
        asm("mov.b64 %0, {%1, %1};" : "=l"(w2) : "f"(w));
        #pragma unroll
        for (int q = 0; q < P; q++) {
            unsigned long long a = *(const unsigned long long*)&base[q * STRIDE + 2 * k];
            asm("fma.rn.f32x2 %0, %1, %2, %0;" : "+l"(acc[q]) : "l"(a), "l"(w2));
        }
    }

    float bc = (EPI == EPI_BIAS_RELU) ? __ldg(&bias[c]) : 0.0f;

    #pragma unroll
    for (int q = 0; q < P; q++) {
        float lo, hi;
        asm("mov.b64 {%0, %1}, %2;" : "=f"(lo), "=f"(hi) : "l"(acc[q]));
        int r0 = row0 + rg * R + 2 * q;
        if (EPI == EPI_DINV) {
            if (r0 < n)     out[(size_t)r0 * FOUT + c]       = lo * g_dinv[r0];
            if (r0 + 1 < n) out[(size_t)(r0 + 1) * FOUT + c] = hi * g_dinv[r0 + 1];
        } else {
            if (r0 < n)     out[(size_t)r0 * FOUT + c]       = fmaxf(lo + bc, 0.0f);
            if (r0 + 1 < n) out[(size_t)(r0 + 1) * FOUT + c] = fmaxf(hi + bc, 0.0f);
        }
    }
}

// Special GEMM for layer 5 (FIN=16, FOUT=2)
__global__ void k_gemm5(const float* __restrict__ A, const float* __restrict__ W,
                        float* __restrict__ out, int n) {
    __shared__ float sW[32];
    if (threadIdx.x < 32) sW[threadIdx.x] = W[threadIdx.x];
    __syncthreads();
    int row = blockIdx.x * blockDim.x + threadIdx.x;
    if (row >= n) return;
    const float4* a4 = (const float4*)(A + (size_t)row * 16);
    float acc0 = 0.0f, acc1 = 0.0f;
    #pragma unroll
    for (int q = 0; q < 4; q++) {
        float4 a = __ldg(&a4[q]);
        acc0 = fmaf(a.x, sW[(4*q+0)*2+0], acc0);
        acc1 = fmaf(a.x, sW[(4*q+0)*2+1], acc1);
        acc0 = fmaf(a.y, sW[(4*q+1)*2+0], acc0);
        acc1 = fmaf(a.y, sW[(4*q+1)*2+1], acc1);
        acc0 = fmaf(a.z, sW[(4*q+2)*2+0], acc0);
        acc1 = fmaf(a.z, sW[(4*q+2)*2+1], acc1);
        acc0 = fmaf(a.w, sW[(4*q+3)*2+0], acc0);
        acc1 = fmaf(a.w, sW[(4*q+3)*2+1], acc1);
    }
    float di = g_dinv[row];
    out[(size_t)row * 2 + 0] = acc0 * di;
    out[(size_t)row * 2 + 1] = acc1 * di;
}

// ---------------- aggregation ---------------------------------------------------
// sum = tmp'[self] + sum_nbr tmp'[src]   (tmp' already carries dinv[src])
// MODE AGG_RELU:      out = relu(b + dinv*sum)
// MODE AGG_RELU_DINV: out = relu(b + dinv*sum) * dinv
// MODE AGG_PRE:       out = dinv*sum
template <int FOUT, int MODE>
__global__ void k_agg(const float* __restrict__ tmp, const float* __restrict__ bias,
                      float* __restrict__ out, int n) {
    constexpr int G = FOUT / 4;
    int t = blockIdx.x * blockDim.x + threadIdx.x;
    int node = t / G;
    int lane = t % G;
    if (node >= n) return;

    const float4* t4 = (const float4*)tmp;
    size_t base = (size_t)node * G + lane;
    float4 acc = __ldg(&t4[base]);  // self-loop term

    int start = g_rowstart[node];
    int c = g_cnt[node];
    int j = 0;
    for (; j + 4 <= c; j += 4) {
        int s0 = __ldg(&g_csrc[start + j + 0]);
        int s1 = __ldg(&g_csrc[start + j + 1]);
        int s2 = __ldg(&g_csrc[start + j + 2]);
        int s3 = __ldg(&g_csrc[start + j + 3]);
        float4 v0 = __ldg(&t4[(size_t)s0 * G + lane]);
        float4 v1 = __ldg(&t4[(size_t)s1 * G + lane]);
        float4 v2 = __ldg(&t4[(size_t)s2 * G + lane]);
        float4 v3 = __ldg(&t4[(size_t)s3 * G + lane]);
        acc.x += (v0.x + v1.x) + (v2.x + v3.x);
        acc.y += (v0.y + v1.y) + (v2.y + v3.y);
        acc.z += (v0.z + v1.z) + (v2.z + v3.z);
        acc.w += (v0.w + v1.w) + (v2.w + v3.w);
    }
    for (; j < c; j++) {
        int s = __ldg(&g_csrc[start + j]);
        float4 v = __ldg(&t4[(size_t)s * G + lane]);
        acc.x += v.x; acc.y += v.y; acc.z += v.z; acc.w += v.w;
    }

    float di = g_dinv[node];
    float4 r;
    if (MODE == AGG_PRE) {
        r.x = di * acc.x; r.y = di * acc.y; r.z = di * acc.z; r.w = di * acc.w;
    } else {
        float4 b = __ldg(&((const float4*)bias)[lane]);
        r.x = fmaxf(fmaf(di, acc.x, b.x), 0.0f);
        r.y = fmaxf(fmaf(di, acc.y, b.y), 0.0f);
        r.z = fmaxf(fmaf(di, acc.z, b.z), 0.0f);
        r.w = fmaxf(fmaf(di, acc.w, b.w), 0.0f);
        if (MODE == AGG_RELU_DINV) {
            r.x *= di; r.y *= di; r.z *= di; r.w *= di;
        }
    }
    ((float4*)out)[base] = r;
}

// Final layer: aggregate Fout=2 and fuse log_softmax, write directly to d_out
__global__ void k_agg_final(const float* __restrict__ tmp, const float* __restrict__ bias,
                            float* __restrict__ out, int n) {
    int node = blockIdx.x * blockDim.x + threadIdx.x;
    if (node >= n) return;
    const float2* t2 = (const float2*)tmp;
    float2 acc = __ldg(&t2[node]);  // self
    int start = g_rowstart[node];
    int c = g_cnt[node];
    int j = 0;
    for (; j + 4 <= c; j += 4) {
        int s0 = __ldg(&g_csrc[start + j + 0]);
        int s1 = __ldg(&g_csrc[start + j + 1]);
        int s2 = __ldg(&g_csrc[start + j + 2]);
        int s3 = __ldg(&g_csrc[start + j + 3]);
        float2 v0 = __ldg(&t2[s0]);
        float2 v1 = __ldg(&t2[s1]);
        float2 v2 = __ldg(&t2[s2]);
        float2 v3 = __ldg(&t2[s3]);
        acc.x += (v0.x + v1.x) + (v2.x + v3.x);
        acc.y += (v0.y + v1.y) + (v2.y + v3.y);
    }
    for (; j < c; j++) {
        float2 v = __ldg(&t2[__ldg(&g_csrc[start + j])]);
        acc.x += v.x; acc.y += v.y;
    }
    float di = g_dinv[node];
    float z0 = fmaf(di, acc.x, bias[0]);
    float z1 = fmaf(di, acc.y, bias[1]);
    float m = fmaxf(z0, z1);
    float l = m + logf(expf(z0 - m) + expf(z1 - m));
    out[(size_t)node * 2 + 0] = z0 - l;
    out[(size_t)node * 2 + 1] = z1 - l;
}

// ---------------- launch -------------------------------------------------------
extern "C" void kernel_launch(void* const* d_in, const int* in_sizes, int n_in,
                              void* d_out, int out_size) {
    const float* x  = (const float*)d_in[0];
    const void*  ei = d_in[1];
    const float* W1 = (const float*)d_in[2];  const float* b1 = (const float*)d_in[3];
    const float* W2 = (const float*)d_in[4];  const float* b2 = (const float*)d_in[5];
    const float* W3 = (const float*)d_in[6];  const float* b3 = (const float*)d_in[7];
    const float* W4 = (const float*)d_in[8];  const float* b4 = (const float*)d_in[9];
    const float* W5 = (const float*)d_in[10]; const float* b5 = (const float*)d_in[11];

    int n = in_sizes[0] / 256;  // 100000
    int e = in_sizes[1] / 2;    // 3200000

    float* tmp_p = nullptr;
    float* h_p   = nullptr;
    cudaGetSymbolAddress((void**)&tmp_p, g_tmp);
    cudaGetSymbolAddress((void**)&h_p,   g_h);

    int nb_n = (n + 255) / 256;   // 391
    int nb_e = (e + 255) / 256;

    // graph preprocessing (recomputed every call — deterministic work)
    k_detect<<<1, 1>>>((const int*)ei);
    k_zero_cnt<<<nb_n, 256>>>(n);
    k_count<<<nb_e, 256>>>(ei, e, n);
    k_bsum<<<nb_n, 256>>>(n);
    k_bscan<<<1, 512>>>(nb_n);
    k_final<<<nb_n, 256>>>(n);
    k_scatter<<<nb_e, 256>>>(ei, e, n);

    int gemm_blocks = (n + 31) / 32;

    // Layer 1: 256 -> 64 (transform-first; agg output pre-scaled by dinv for L2)
    k_gemm<256, 64, EPI_DINV><<<gemm_blocks, 256>>>(x, W1, tmp_p, nullptr, n);
    k_agg<64, AGG_RELU_DINV><<<((size_t)n * 16 + 255) / 256, 256>>>(tmp_p, b1, h_p, n);
    // Layer 2: 64 -> 128 (aggregate-FIRST: gather at F=64, then GEMM w/ bias+relu)
    k_agg<64, AGG_PRE><<<((size_t)n * 16 + 255) / 256, 256>>>(h_p, nullptr, tmp_p, n);
    k_gemm<64, 128, EPI_BIAS_RELU><<<gemm_blocks, 256>>>(tmp_p, W2, h_p, b2, n);
    // Layer 3: 128 -> 64 (transform-first)
    k_gemm<128, 64, EPI_DINV><<<gemm_blocks, 256>>>(h_p, W3, tmp_p, nullptr, n);
    k_agg<64, AGG_RELU><<<((size_t)n * 16 + 255) / 256, 256>>>(tmp_p, b3, h_p, n);
    // Layer 4: 64 -> 16
    k_gemm<64, 16, EPI_DINV><<<gemm_blocks, 256>>>(h_p, W4, tmp_p, nullptr, n);
    k_agg<16, AGG_RELU><<<((size_t)n * 4 + 255) / 256, 256>>>(tmp_p, b4, h_p, n);
    // Layer 5: 16 -> 2, fused log_softmax
    k_gemm5<<<nb_n, 256>>>(h_p, W5, tmp_p, n);
    k_agg_final<<<nb_n, 256>>>(tmp_p, b5, (float*)d_out, n);
}

// round 5
// speedup vs baseline: 1.5313x; 1.1134x over previous
#include <cuda_runtime.h>
#include <cuda_fp16.h>
#include <math.h>

// Problem constants (fixed by the dataset)
#define N_MAX 100000
#define E_MAX 3200000
#define FMAX  128

// ---------------- device scratch ----------------------------------------------
__device__ float g_dinv[N_MAX];
__device__ int   g_cnt[N_MAX];
__device__ int   g_rowstart[N_MAX];
__device__ int   g_cursor[N_MAX];
__device__ int   g_csrc[E_MAX];
__device__ float g_tmp[(size_t)N_MAX * FMAX];   // generic buffer A (fp32 or fp16 view)
__device__ float g_h[(size_t)N_MAX * FMAX];     // generic buffer B
__device__ int   g_is64;
__device__ int   g_bsum[512];
__device__ int   g_boff[512];

// Epilogue modes
#define EPI_DINV      0   // out = acc * dinv[row]              (transform-first)
#define EPI_BIAS_RELU 1   // out = relu(acc + bias[c])          (aggregate-first)

#define AGG_RELU      0   // out = relu(b + dinv*sum)
#define AGG_RELU_DINV 1   // out = relu(b + dinv*sum) * dinv    (pre-scaled for next agg)
#define AGG_PRE       2   // out = dinv*sum                     (no bias/relu)

// ---------------- graph preprocessing ----------------------------------------

__global__ void k_zero_cnt(int n) {
    int i = blockIdx.x * blockDim.x + threadIdx.x;
    if (i < n) g_cnt[i] = 0;
}

// Detect int64 vs int32 edge buffer: int64 values < 2^31 have zero odd words.
__global__ void k_detect(const int* __restrict__ w) {
    int z = 0;
    #pragma unroll
    for (int i = 0; i < 64; i++) z |= w[2 * i + 1];
    g_is64 = (z == 0) ? 1 : 0;
}

// count in-degree, reading dst directly from the edge buffer
__global__ void k_count(const void* __restrict__ ei, int e, int n) {
    int t = blockIdx.x * blockDim.x + threadIdx.x;
    if (t >= e) return;
    int d;
    if (g_is64) d = (int)((const long long*)ei)[(size_t)e + t];
    else        d = ((const int*)ei)[e + t];
    if ((unsigned)d < (unsigned)n) atomicAdd(&g_cnt[d], 1);
}

// per-block sums of g_cnt
__global__ void k_bsum(int n) {
    int i = blockIdx.x * 256 + threadIdx.x;
    int v = (i < n) ? g_cnt[i] : 0;
    #pragma unroll
    for (int o = 16; o; o >>= 1) v += __shfl_down_sync(0xFFFFFFFFu, v, o);
    __shared__ int ws[8];
    if ((threadIdx.x & 31) == 0) ws[threadIdx.x >> 5] = v;
    __syncthreads();
    if (threadIdx.x == 0) {
        int s = 0;
        #pragma unroll
        for (int j = 0; j < 8; j++) s += ws[j];
        g_bsum[blockIdx.x] = s;
    }
}

// single-block exclusive scan of block sums (nb <= 512)
__global__ void k_bscan(int nb) {
    __shared__ int sm[512];
    int t = threadIdx.x;
    int v = (t < nb) ? g_bsum[t] : 0;
    sm[t] = v;
    __syncthreads();
    for (int o = 1; o < 512; o <<= 1) {
        int y = (t >= o) ? sm[t - o] : 0;
        __syncthreads();
        sm[t] += y;
        __syncthreads();
    }
    if (t < nb) g_boff[t] = sm[t] - v;
}

// per-block exclusive scan + rowstart/cursor/dinv in one pass
__global__ void k_final(int n) {
    int i = blockIdx.x * 256 + threadIdx.x;
    int v = (i < n) ? g_cnt[i] : 0;
    int lane = threadIdx.x & 31, wid = threadIdx.x >> 5;
    int x = v;
    #pragma unroll
    for (int o = 1; o < 32; o <<= 1) {
        int y = __shfl_up_sync(0xFFFFFFFFu, x, o);
        if (lane >= o) x += y;
    }
    __shared__ int ws[8];
    if (lane == 31) ws[wid] = x;
    __syncthreads();
    if (threadIdx.x < 8) {
        int y = ws[threadIdx.x];
        int z = y;
        #pragma unroll
        for (int o = 1; o < 8; o <<= 1) {
            int t2 = __shfl_up_sync(0xFFu, z, o);
            if (threadIdx.x >= o) z += t2;
        }
        ws[threadIdx.x] = z - y;  // exclusive warp offset
    }
    __syncthreads();
    if (i < n) {
        int excl = (x - v) + ws[wid] + g_boff[blockIdx.x];
        g_rowstart[i] = excl;
        g_cursor[i]   = excl;
        g_dinv[i]     = rsqrtf((float)(v + 1));  // +1 = self loop
    }
}

// scatter sources into CSR-by-destination (reads edge buffer directly)
__global__ void k_scatter(const void* __restrict__ ei, int e, int n) {
    int t = blockIdx.x * blockDim.x + threadIdx.x;
    if (t >= e) return;
    int s, d;
    if (g_is64) {
        const long long* p = (const long long*)ei;
        s = (int)p[t];
        d = (int)p[(size_t)e + t];
    } else {
        const int* p = (const int*)ei;
        s = p[t];
        d = p[e + t];
    }
    if ((unsigned)s >= (unsigned)n || (unsigned)d >= (unsigned)n) return;
    int pos = atomicAdd(&g_cursor[d], 1);
    g_csrc[pos] = s;
}

// ---------------- GEMM with selectable epilogue / output dtype -----------------
// Pair-interleaved smem tile + packed fma.rn.f32x2 (2 rows per FMA instruction).
template <int FIN, int FOUT, int EPI, bool OUTH>
__global__ void k_gemm(const float* __restrict__ A, const float* __restrict__ W,
                       void* __restrict__ outv, const float* __restrict__ bias, int n) {
    constexpr int ROWS = 32;
    constexpr int G = 256 / FOUT;   // row groups per block
    constexpr int R = ROWS / G;     // rows per thread (even)
    constexpr int P = R / 2;        // row pairs per thread
    constexpr int STRIDE = 2 * FIN + 2;
    __shared__ __align__(16) float sP[(ROWS / 2) * STRIDE];

    int row0 = blockIdx.x * ROWS;

    // writer: lane = row, warp strides over k4 chunks
    {
        int lane = threadIdx.x & 31, w = threadIdx.x >> 5;
        int grow = row0 + lane;
        float* dst = &sP[(lane >> 1) * STRIDE + (lane & 1)];
        const float4* src = (const float4*)(A + (size_t)grow * FIN);
        for (int k4 = w; k4 < FIN / 4; k4 += 8) {
            float4 a = (grow < n) ? __ldg(&src[k4]) : make_float4(0.f, 0.f, 0.f, 0.f);
            dst[2 * (4 * k4 + 0)] = a.x;
            dst[2 * (4 * k4 + 1)] = a.y;
            dst[2 * (4 * k4 + 2)] = a.z;
            dst[2 * (4 * k4 + 3)] = a.w;
        }
    }
    __syncthreads();

    int c  = threadIdx.x % FOUT;
    int rg = threadIdx.x / FOUT;

    unsigned long long acc[P];
    #pragma unroll
    for (int q = 0; q < P; q++) acc[q] = 0ULL;

    const float* base = &sP[(rg * P) * STRIDE];

    #pragma unroll 4
    for (int k = 0; k < FIN; k++) {
        float w = __ldg(&W[k * FOUT + c]);
        unsigned long long w2;
        asm("mov.b64 %0, {%1, %1};" : "=l"(w2) : "f"(w));
        #pragma unroll
        for (int q = 0; q < P; q++) {
            unsigned long long a = *(const unsigned long long*)&base[q * STRIDE + 2 * k];
            asm("fma.rn.f32x2 %0, %1, %2, %0;" : "+l"(acc[q]) : "l"(a), "l"(w2));
        }
    }

    float bc = (EPI == EPI_BIAS_RELU) ? __ldg(&bias[c]) : 0.0f;

    #pragma unroll
    for (int q = 0; q < P; q++) {
        float lo, hi;
        asm("mov.b64 {%0, %1}, %2;" : "=f"(lo), "=f"(hi) : "l"(acc[q]));
        int r0 = row0 + rg * R + 2 * q;
        float v0, v1;
        if (EPI == EPI_DINV) {
            v0 = lo * ((r0 < n) ? g_dinv[r0] : 0.f);
            v1 = hi * ((r0 + 1 < n) ? g_dinv[r0 + 1] : 0.f);
        } else {
            v0 = fmaxf(lo + bc, 0.0f);
            v1 = fmaxf(hi + bc, 0.0f);
        }
        if (OUTH) {
            __half* out = (__half*)outv;
            if (r0 < n)     out[(size_t)r0 * FOUT + c]       = __float2half_rn(v0);
            if (r0 + 1 < n) out[(size_t)(r0 + 1) * FOUT + c] = __float2half_rn(v1);
        } else {
            float* out = (float*)outv;
            if (r0 < n)     out[(size_t)r0 * FOUT + c]       = v0;
            if (r0 + 1 < n) out[(size_t)(r0 + 1) * FOUT + c] = v1;
        }
    }
}

// Special GEMM for layer 5 (FIN=16, FOUT=2)
__global__ void k_gemm5(const float* __restrict__ A, const float* __restrict__ W,
                        float* __restrict__ out, int n) {
    __shared__ float sW[32];
    if (threadIdx.x < 32) sW[threadIdx.x] = W[threadIdx.x];
    __syncthreads();
    int row = blockIdx.x * blockDim.x + threadIdx.x;
    if (row >= n) return;
    const float4* a4 = (const float4*)(A + (size_t)row * 16);
    float acc0 = 0.0f, acc1 = 0.0f;
    #pragma unroll
    for (int q = 0; q < 4; q++) {
        float4 a = __ldg(&a4[q]);
        acc0 = fmaf(a.x, sW[(4*q+0)*2+0], acc0);
        acc1 = fmaf(a.x, sW[(4*q+0)*2+1], acc1);
        acc0 = fmaf(a.y, sW[(4*q+1)*2+0], acc0);
        acc1 = fmaf(a.y, sW[(4*q+1)*2+1], acc1);
        acc0 = fmaf(a.z, sW[(4*q+2)*2+0], acc0);
        acc1 = fmaf(a.z, sW[(4*q+2)*2+1], acc1);
        acc0 = fmaf(a.w, sW[(4*q+3)*2+0], acc0);
        acc1 = fmaf(a.w, sW[(4*q+3)*2+1], acc1);
    }
    float di = g_dinv[row];
    out[(size_t)row * 2 + 0] = acc0 * di;
    out[(size_t)row * 2 + 1] = acc1 * di;
}

// ---------------- fp16 gather aggregation --------------------------------------
__device__ __forceinline__ void add8(float* a, uint4 v) {
    __half2 h0 = *reinterpret_cast<__half2*>(&v.x);
    __half2 h1 = *reinterpret_cast<__half2*>(&v.y);
    __half2 h2 = *reinterpret_cast<__half2*>(&v.z);
    __half2 h3 = *reinterpret_cast<__half2*>(&v.w);
    float2 f0 = __half22float2(h0);
    float2 f1 = __half22float2(h1);
    float2 f2 = __half22float2(h2);
    float2 f3 = __half22float2(h3);
    a[0] += f0.x; a[1] += f0.y; a[2] += f1.x; a[3] += f1.y;
    a[4] += f2.x; a[5] += f2.y; a[6] += f3.x; a[7] += f3.y;
}

// sum = tmp'[self] + sum_nbr tmp'[src]  (fp16 storage, fp32 accumulation)
template <int F, int MODE, bool OUTH>
__global__ void k_agg_h(const __half* __restrict__ tmp, const float* __restrict__ bias,
                        void* __restrict__ outv, int n) {
    constexpr int G = F / 8;   // lanes per node (8 halves = 16B per lane)
    int t = blockIdx.x * blockDim.x + threadIdx.x;
    int node = t / G;
    int lane = t % G;
    if (node >= n) return;

    const uint4* t4 = (const uint4*)tmp;
    size_t base = (size_t)node * G + lane;

    float acc[8] = {0, 0, 0, 0, 0, 0, 0, 0};
    add8(acc, __ldg(&t4[base]));  // self-loop term

    int start = g_rowstart[node];
    int c = g_cnt[node];
    int j = 0;
    for (; j + 4 <= c; j += 4) {
        int s0 = __ldg(&g_csrc[start + j + 0]);
        int s1 = __ldg(&g_csrc[start + j + 1]);
        int s2 = __ldg(&g_csrc[start + j + 2]);
        int s3 = __ldg(&g_csrc[start + j + 3]);
        uint4 v0 = __ldg(&t4[(size_t)s0 * G + lane]);
        uint4 v1 = __ldg(&t4[(size_t)s1 * G + lane]);
        uint4 v2 = __ldg(&t4[(size_t)s2 * G + lane]);
        uint4 v3 = __ldg(&t4[(size_t)s3 * G + lane]);
        add8(acc, v0); add8(acc, v1); add8(acc, v2); add8(acc, v3);
    }
    for (; j < c; j++) {
        int s = __ldg(&g_csrc[start + j]);
        add8(acc, __ldg(&t4[(size_t)s * G + lane]));
    }

    float di = g_dinv[node];
    float r[8];
    if (MODE == AGG_PRE) {
        #pragma unroll
        for (int i = 0; i < 8; i++) r[i] = di * acc[i];
    } else {
        #pragma unroll
        for (int i = 0; i < 8; i++) {
            float b = __ldg(&bias[lane * 8 + i]);
            r[i] = fmaxf(fmaf(di, acc[i], b), 0.0f);
            if (MODE == AGG_RELU_DINV) r[i] *= di;
        }
    }

    if (OUTH) {
        uint4 o;
        __half2 p0 = __floats2half2_rn(r[0], r[1]);
        __half2 p1 = __floats2half2_rn(r[2], r[3]);
        __half2 p2 = __floats2half2_rn(r[4], r[5]);
        __half2 p3 = __floats2half2_rn(r[6], r[7]);
        o.x = *reinterpret_cast<unsigned*>(&p0);
        o.y = *reinterpret_cast<unsigned*>(&p1);
        o.z = *reinterpret_cast<unsigned*>(&p2);
        o.w = *reinterpret_cast<unsigned*>(&p3);
        ((uint4*)outv)[base] = o;
    } else {
        float4* out = (float4*)outv;
        size_t fbase = (size_t)node * (F / 4) + lane * 2;
        out[fbase + 0] = make_float4(r[0], r[1], r[2], r[3]);
        out[fbase + 1] = make_float4(r[4], r[5], r[6], r[7]);
    }
}

// Final layer: aggregate Fout=2 (fp32) and fuse log_softmax, write to d_out
__global__ void k_agg_final(const float* __restrict__ tmp, const float* __restrict__ bias,
                            float* __restrict__ out, int n) {
    int node = blockIdx.x * blockDim.x + threadIdx.x;
    if (node >= n) return;
    const float2* t2 = (const float2*)tmp;
    float2 acc = __ldg(&t2[node]);  // self
    int start = g_rowstart[node];
    int c = g_cnt[node];
    int j = 0;
    for (; j + 4 <= c; j += 4) {
        int s0 = __ldg(&g_csrc[start + j + 0]);
        int s1 = __ldg(&g_csrc[start + j + 1]);
        int s2 = __ldg(&g_csrc[start + j + 2]);
        int s3 = __ldg(&g_csrc[start + j + 3]);
        float2 v0 = __ldg(&t2[s0]);
        float2 v1 = __ldg(&t2[s1]);
        float2 v2 = __ldg(&t2[s2]);
        float2 v3 = __ldg(&t2[s3]);
        acc.x += (v0.x + v1.x) + (v2.x + v3.x);
        acc.y += (v0.y + v1.y) + (v2.y + v3.y);
    }
    for (; j < c; j++) {
        float2 v = __ldg(&t2[__ldg(&g_csrc[start + j])]);
        acc.x += v.x; acc.y += v.y;
    }
    float di = g_dinv[node];
    float z0 = fmaf(di, acc.x, bias[0]);
    float z1 = fmaf(di, acc.y, bias[1]);
    float m = fmaxf(z0, z1);
    float l = m + logf(expf(z0 - m) + expf(z1 - m));
    out[(size_t)node * 2 + 0] = z0 - l;
    out[(size_t)node * 2 + 1] = z1 - l;
}

// ---------------- launch -------------------------------------------------------
extern "C" void kernel_launch(void* const* d_in, const int* in_sizes, int n_in,
                              void* d_out, int out_size) {
    const float* x  = (const float*)d_in[0];
    const void*  ei = d_in[1];
    const float* W1 = (const float*)d_in[2];  const float* b1 = (const float*)d_in[3];
    const float* W2 = (const float*)d_in[4];  const float* b2 = (const float*)d_in[5];
    const float* W3 = (const float*)d_in[6];  const float* b3 = (const float*)d_in[7];
    const float* W4 = (const float*)d_in[8];  const float* b4 = (const float*)d_in[9];
    const float* W5 = (const float*)d_in[10]; const float* b5 = (const float*)d_in[11];

    int n = in_sizes[0] / 256;  // 100000
    int e = in_sizes[1] / 2;    // 3200000

    void* bufA = nullptr;   // g_tmp
    void* bufB = nullptr;   // g_h
    cudaGetSymbolAddress(&bufA, g_tmp);
    cudaGetSymbolAddress(&bufB, g_h);

    int nb_n = (n + 255) / 256;   // 391
    int nb_e = (e + 255) / 256;

    // graph preprocessing (recomputed every call — deterministic work)
    k_detect<<<1, 1>>>((const int*)ei);
    k_zero_cnt<<<nb_n, 256>>>(n);
    k_count<<<nb_e, 256>>>(ei, e, n);
    k_bsum<<<nb_n, 256>>>(n);
    k_bscan<<<1, 512>>>(nb_n);
    k_final<<<nb_n, 256>>>(n);
    k_scatter<<<nb_e, 256>>>(ei, e, n);

    int gemm_blocks = (n + 31) / 32;
    int agg64_blocks = (int)(((size_t)n * 8 + 255) / 256);
    int agg16_blocks = (int)(((size_t)n * 2 + 255) / 256);

    // Layer 1: 256 -> 64 (transform-first; fp16 gather buffers)
    k_gemm<256, 64, EPI_DINV, true><<<gemm_blocks, 256>>>(x, W1, bufA, nullptr, n);
    k_agg_h<64, AGG_RELU_DINV, true><<<agg64_blocks, 256>>>((const __half*)bufA, b1, bufB, n);
    // Layer 2: 64 -> 128 (aggregate-FIRST at F=64 fp16, then GEMM w/ bias+relu)
    k_agg_h<64, AGG_PRE, false><<<agg64_blocks, 256>>>((const __half*)bufB, nullptr, bufA, n);
    k_gemm<64, 128, EPI_BIAS_RELU, false><<<gemm_blocks, 256>>>((const float*)bufA, W2, bufB, b2, n);
    // Layer 3: 128 -> 64 (transform-first)
    k_gemm<128, 64, EPI_DINV, true><<<gemm_blocks, 256>>>((const float*)bufB, W3, bufA, nullptr, n);
    k_agg_h<64, AGG_RELU, false><<<agg64_blocks, 256>>>((const __half*)bufA, b3, bufB, n);
    // Layer 4: 64 -> 16
    k_gemm<64, 16, EPI_DINV, true><<<gemm_blocks, 256>>>((const float*)bufB, W4, bufA, nullptr, n);
    k_agg_h<16, AGG_RELU, false><<<agg16_blocks, 256>>>((const __half*)bufA, b4, bufB, n);
    // Layer 5: 16 -> 2, fp32 throughout, fused log_softmax
    k_gemm5<<<nb_n, 256>>>((const float*)bufB, W5, (float*)bufA, n);
    k_agg_final<<<nb_n, 256>>>((const float*)bufA, b5, (float*)d_out, n);
}

// round 6
// speedup vs baseline: 2.0566x; 1.3430x over previous
#include <cuda_runtime.h>
#include <cuda_fp16.h>
#include <mma.h>
#include <math.h>

using namespace nvcuda;

// Problem constants (fixed by the dataset)
#define N_MAX 100000
#define E_MAX 3200000
#define FMAX  128

// ---------------- device scratch ----------------------------------------------
__device__ float g_dinv[N_MAX];
__device__ int   g_cnt[N_MAX];
__device__ int   g_rowstart[N_MAX];
__device__ int   g_cursor[N_MAX];
__device__ int   g_csrc[E_MAX];
__device__ float g_tmp[(size_t)N_MAX * FMAX];   // generic buffer A
__device__ float g_h[(size_t)N_MAX * FMAX];     // generic buffer B
__device__ int   g_is64;
__device__ int   g_bsum[512];

// Epilogue modes
#define EPI_DINV      0   // out = acc * dinv[row]              (transform-first)
#define EPI_BIAS_RELU 1   // out = relu(acc + bias[c])          (aggregate-first)

#define AGG_RELU      0   // out = relu(b + dinv*sum)
#define AGG_RELU_DINV 1   // out = relu(b + dinv*sum) * dinv    (pre-scaled for next agg)
#define AGG_PRE       2   // out = dinv*sum                     (no bias/relu)

// ---------------- graph preprocessing ----------------------------------------

// zero counters + (block 0) dtype detect in one launch
__global__ void k_init(const int* __restrict__ w, int n) {
    int i = blockIdx.x * blockDim.x + threadIdx.x;
    if (i < n) g_cnt[i] = 0;
    if (blockIdx.x == 0 && threadIdx.x == 0) {
        // int64 values < 2^31 have zero odd 32-bit words; int32 data doesn't.
        int z = 0;
        #pragma unroll
        for (int k = 0; k < 64; k++) z |= w[2 * k + 1];
        g_is64 = (z == 0) ? 1 : 0;
    }
}

// count in-degree, reading dst directly from the edge buffer
__global__ void k_count(const void* __restrict__ ei, int e, int n) {
    int t = blockIdx.x * blockDim.x + threadIdx.x;
    if (t >= e) return;
    int d;
    if (g_is64) d = (int)((const long long*)ei)[(size_t)e + t];
    else        d = ((const int*)ei)[e + t];
    if ((unsigned)d < (unsigned)n) atomicAdd(&g_cnt[d], 1);
}

// per-block sums of g_cnt
__global__ void k_bsum(int n) {
    int i = blockIdx.x * 256 + threadIdx.x;
    int v = (i < n) ? g_cnt[i] : 0;
    #pragma unroll
    for (int o = 16; o; o >>= 1) v += __shfl_down_sync(0xFFFFFFFFu, v, o);
    __shared__ int ws[8];
    if ((threadIdx.x & 31) == 0) ws[threadIdx.x >> 5] = v;
    __syncthreads();
    if (threadIdx.x == 0) {
        int s = 0;
        #pragma unroll
        for (int j = 0; j < 8; j++) s += ws[j];
        g_bsum[blockIdx.x] = s;
    }
}

// per-block scan; each block derives its own global offset from g_bsum[0..bid)
__global__ void k_final(int n, int nb) {
    // 1) block offset = sum of g_bsum[0..blockIdx.x)
    __shared__ int s_off;
    {
        int p = 0;
        for (int i = threadIdx.x; i < blockIdx.x; i += 256) p += g_bsum[i];
        #pragma unroll
        for (int o = 16; o; o >>= 1) p += __shfl_down_sync(0xFFFFFFFFu, p, o);
        __shared__ int ws2[8];
        if ((threadIdx.x & 31) == 0) ws2[threadIdx.x >> 5] = p;
        __syncthreads();
        if (threadIdx.x == 0) {
            int s = 0;
            #pragma unroll
            for (int j = 0; j < 8; j++) s += ws2[j];
            s_off = s;
        }
    }
    // 2) intra-block exclusive scan
    int i = blockIdx.x * 256 + threadIdx.x;
    int v = (i < n) ? g_cnt[i] : 0;
    int lane = threadIdx.x & 31, wid = threadIdx.x >> 5;
    int x = v;
    #pragma unroll
    for (int o = 1; o < 32; o <<= 1) {
        int y = __shfl_up_sync(0xFFFFFFFFu, x, o);
        if (lane >= o) x += y;
    }
    __shared__ int ws[8];
    if (lane == 31) ws[wid] = x;
    __syncthreads();
    if (threadIdx.x < 8) {
        int y = ws[threadIdx.x];
        int z = y;
        #pragma unroll
        for (int o = 1; o < 8; o <<= 1) {
            int t2 = __shfl_up_sync(0xFFu, z, o);
            if (threadIdx.x >= o) z += t2;
        }
        ws[threadIdx.x] = z - y;  // exclusive warp offset
    }
    __syncthreads();
    if (i < n) {
        int excl = (x - v) + ws[wid] + s_off;
        g_rowstart[i] = excl;
        g_cursor[i]   = excl;
        g_dinv[i]     = rsqrtf((float)(v + 1));  // +1 = self loop
    }
}

// scatter sources into CSR-by-destination (reads edge buffer directly)
__global__ void k_scatter(const void* __restrict__ ei, int e, int n) {
    int t = blockIdx.x * blockDim.x + threadIdx.x;
    if (t >= e) return;
    int s, d;
    if (g_is64) {
        const long long* p = (const long long*)ei;
        s = (int)p[t];
        d = (int)p[(size_t)e + t];
    } else {
        const int* p = (const int*)ei;
        s = p[t];
        d = p[e + t];
    }
    if ((unsigned)s >= (unsigned)n || (unsigned)d >= (unsigned)n) return;
    int pos = atomicAdd(&g_cursor[d], 1);
    g_csrc[pos] = s;
}

// ---------------- tf32 tensor-core GEMM ----------------------------------------
// 32 rows/block, 128 threads (4 warps). K staged in 64-wide smem chunks.
// Warp w owns col tiles {w, w+4, ...} x row tiles {0,1}; m16n16k8 tf32 WMMA.
template <int FIN, int FOUT, int EPI, bool OUTH>
__global__ void k_gemm_tc(const float* __restrict__ A, const float* __restrict__ W,
                          void* __restrict__ outv, const float* __restrict__ bias, int n) {
    constexpr int KC = 64;            // k-chunk
    constexpr int NCH = FIN / KC;     // chunks
    constexpr int SA_LD = KC + 8;     // 72
    constexpr int SW_LD = FOUT + 4;
    constexpr int CT = FOUT / 16;     // col tiles
    constexpr int CPW = CT / 4;       // col tiles per warp

    __shared__ float sA[32 * SA_LD];
    __shared__ float sW[KC * SW_LD];  // also reused as epilogue buffer (32*FOUT <= KC*SW_LD)

    int row0 = blockIdx.x * 32;
    int t = threadIdx.x;
    int w = t >> 5;

    wmma::fragment<wmma::accumulator, 16, 16, 8, float> acc[2][CPW];
    #pragma unroll
    for (int r = 0; r < 2; r++)
        #pragma unroll
        for (int j = 0; j < CPW; j++) wmma::fill_fragment(acc[r][j], 0.0f);

    for (int kc = 0; kc < NCH; kc++) {
        // stage A chunk: 32 rows x 64 cols (tf32-rounded)
        #pragma unroll
        for (int it = 0; it < 4; it++) {
            int idx = t + it * 128;          // float4 index within 32x64
            int r = idx >> 4, c4 = idx & 15;
            int grow = row0 + r;
            float4 a = (grow < n) ? __ldg((const float4*)(A + (size_t)grow * FIN + kc * KC + c4 * 4))
                                  : make_float4(0.f, 0.f, 0.f, 0.f);
            float* d = &sA[r * SA_LD + c4 * 4];
            d[0] = wmma::__float_to_tf32(a.x);
            d[1] = wmma::__float_to_tf32(a.y);
            d[2] = wmma::__float_to_tf32(a.z);
            d[3] = wmma::__float_to_tf32(a.w);
        }
        // stage W chunk: 64 k-rows x FOUT cols
        #pragma unroll
        for (int it = 0; it < KC * FOUT / 4 / 128; it++) {
            int idx = t + it * 128;
            int k = idx / (FOUT / 4), c4 = idx % (FOUT / 4);
            float4 v = __ldg((const float4*)(W + (size_t)(kc * KC + k) * FOUT + c4 * 4));
            float* d = &sW[k * SW_LD + c4 * 4];
            d[0] = wmma::__float_to_tf32(v.x);
            d[1] = wmma::__float_to_tf32(v.y);
            d[2] = wmma::__float_to_tf32(v.z);
            d[3] = wmma::__float_to_tf32(v.w);
        }
        __syncthreads();

        #pragma unroll
        for (int ks = 0; ks < KC / 8; ks++) {
            wmma::fragment<wmma::matrix_a, 16, 16, 8, wmma::precision::tf32, wmma::row_major> a0, a1;
            wmma::load_matrix_sync(a0, &sA[ks * 8], SA_LD);
            wmma::load_matrix_sync(a1, &sA[16 * SA_LD + ks * 8], SA_LD);
            #pragma unroll
            for (int j = 0; j < CPW; j++) {
                wmma::fragment<wmma::matrix_b, 16, 16, 8, wmma::precision::tf32, wmma::row_major> b;
                wmma::load_matrix_sync(b, &sW[ks * 8 * SW_LD + (w + j * 4) * 16], SW_LD);
                wmma::mma_sync(acc[0][j], a0, b, acc[0][j]);
                wmma::mma_sync(acc[1][j], a1, b, acc[1][j]);
            }
        }
        __syncthreads();
    }

    // epilogue: frags -> smem -> global with dinv / bias+relu, optional fp16
    float* sEp = sW;  // 32*FOUT floats fit
    #pragma unroll
    for (int r = 0; r < 2; r++)
        #pragma unroll
        for (int j = 0; j < CPW; j++)
            wmma::store_matrix_sync(&sEp[r * 16 * FOUT + (w + j * 4) * 16], acc[r][j],
                                    FOUT, wmma::mem_row_major);
    __syncthreads();

    #pragma unroll
    for (int it = 0; it < 32 * FOUT / 4 / 128; it++) {
        int idx = t + it * 128;
        int r = idx / (FOUT / 4), c4 = idx % (FOUT / 4);
        int grow = row0 + r;
        if (grow >= n) continue;
        float4 v = *(const float4*)&sEp[r * FOUT + c4 * 4];
        if (EPI == EPI_DINV) {
            float di = g_dinv[grow];
            v.x *= di; v.y *= di; v.z *= di; v.w *= di;
        } else {
            const float4 bb = __ldg((const float4*)(bias + c4 * 4));
            v.x = fmaxf(v.x + bb.x, 0.f);
            v.y = fmaxf(v.y + bb.y, 0.f);
            v.z = fmaxf(v.z + bb.z, 0.f);
            v.w = fmaxf(v.w + bb.w, 0.f);
        }
        if (OUTH) {
            __half2 p0 = __floats2half2_rn(v.x, v.y);
            __half2 p1 = __floats2half2_rn(v.z, v.w);
            uint2 o;
            o.x = *reinterpret_cast<unsigned*>(&p0);
            o.y = *reinterpret_cast<unsigned*>(&p1);
            *(uint2*)((__half*)outv + (size_t)grow * FOUT + c4 * 4) = o;
        } else {
            *(float4*)((float*)outv + (size_t)grow * FOUT + c4 * 4) = v;
        }
    }
}

// ---------------- scalar GEMM (layer 4: 64 -> 16) -------------------------------
template <int FIN, int FOUT, int EPI, bool OUTH>
__global__ void k_gemm(const float* __restrict__ A, const float* __restrict__ W,
                       void* __restrict__ outv, const float* __restrict__ bias, int n) {
    constexpr int ROWS = 32;
    constexpr int G = 256 / FOUT;
    constexpr int R = ROWS / G;
    constexpr int P = R / 2;
    constexpr int STRIDE = 2 * FIN + 2;
    __shared__ __align__(16) float sP[(ROWS / 2) * STRIDE];

    int row0 = blockIdx.x * ROWS;
    {
        int lane = threadIdx.x & 31, w = threadIdx.x >> 5;
        int grow = row0 + lane;
        float* dst = &sP[(lane >> 1) * STRIDE + (lane & 1)];
        const float4* src = (const float4*)(A + (size_t)grow * FIN);
        for (int k4 = w; k4 < FIN / 4; k4 += 8) {
            float4 a = (grow < n) ? __ldg(&src[k4]) : make_float4(0.f, 0.f, 0.f, 0.f);
            dst[2 * (4 * k4 + 0)] = a.x;
            dst[2 * (4 * k4 + 1)] = a.y;
            dst[2 * (4 * k4 + 2)] = a.z;
            dst[2 * (4 * k4 + 3)] = a.w;
        }
    }
    __syncthreads();

    int c  = threadIdx.x % FOUT;
    int rg = threadIdx.x / FOUT;

    unsigned long long acc[P];
    #pragma unroll
    for (int q = 0; q < P; q++) acc[q] = 0ULL;
    const float* base = &sP[(rg * P) * STRIDE];

    #pragma unroll 4
    for (int k = 0; k < FIN; k++) {
        float w = __ldg(&W[k * FOUT + c]);
        unsigned long long w2;
        asm("mov.b64 %0, {%1, %1};" : "=l"(w2) : "f"(w));
        #pragma unroll
        for (int q = 0; q < P; q++) {
            unsigned long long a = *(const unsigned long long*)&base[q * STRIDE + 2 * k];
            asm("fma.rn.f32x2 %0, %1, %2, %0;" : "+l"(acc[q]) : "l"(a), "l"(w2));
        }
    }

    float bc = (EPI == EPI_BIAS_RELU) ? __ldg(&bias[c]) : 0.0f;
    #pragma unroll
    for (int q = 0; q < P; q++) {
        float lo, hi;
        asm("mov.b64 {%0, %1}, %2;" : "=f"(lo), "=f"(hi) : "l"(acc[q]));
        int r0 = row0 + rg * R + 2 * q;
        float v0, v1;
        if (EPI == EPI_DINV) {
            v0 = lo * ((r0 < n) ? g_dinv[r0] : 0.f);
            v1 = hi * ((r0 + 1 < n) ? g_dinv[r0 + 1] : 0.f);
        } else {
            v0 = fmaxf(lo + bc, 0.0f);
            v1 = fmaxf(hi + bc, 0.0f);
        }
        if (OUTH) {
            __half* out = (__half*)outv;
            if (r0 < n)     out[(size_t)r0 * FOUT + c]       = __float2half_rn(v0);
            if (r0 + 1 < n) out[(size_t)(r0 + 1) * FOUT + c] = __float2half_rn(v1);
        } else {
            float* out = (float*)outv;
            if (r0 < n)     out[(size_t)r0 * FOUT + c]       = v0;
            if (r0 + 1 < n) out[(size_t)(r0 + 1) * FOUT + c] = v1;
        }
    }
}

// Special GEMM for layer 5 (FIN=16, FOUT=2)
__global__ void k_gemm5(const float* __restrict__ A, const float* __restrict__ W,
                        float* __restrict__ out, int n) {
    __shared__ float sW[32];
    if (threadIdx.x < 32) sW[threadIdx.x] = W[threadIdx.x];
    __syncthreads();
    int row = blockIdx.x * blockDim.x + threadIdx.x;
    if (row >= n) return;
    const float4* a4 = (const float4*)(A + (size_t)row * 16);
    float acc0 = 0.0f, acc1 = 0.0f;
    #pragma unroll
    for (int q = 0; q < 4; q++) {
        float4 a = __ldg(&a4[q]);
        acc0 = fmaf(a.x, sW[(4*q+0)*2+0], acc0);
        acc1 = fmaf(a.x, sW[(4*q+0)*2+1], acc1);
        acc0 = fmaf(a.y, sW[(4*q+1)*2+0], acc0);
        acc1 = fmaf(a.y, sW[(4*q+1)*2+1], acc1);
        acc0 = fmaf(a.z, sW[(4*q+2)*2+0], acc0);
        acc1 = fmaf(a.z, sW[(4*q+2)*2+1], acc1);
        acc0 = fmaf(a.w, sW[(4*q+3)*2+0], acc0);
        acc1 = fmaf(a.w, sW[(4*q+3)*2+1], acc1);
    }
    float di = g_dinv[row];
    out[(size_t)row * 2 + 0] = acc0 * di;
    out[(size_t)row * 2 + 1] = acc1 * di;
}

// ---------------- fp16 gather aggregation --------------------------------------
__device__ __forceinline__ void add8(float* a, uint4 v) {
    __half2 h0 = *reinterpret_cast<__half2*>(&v.x);
    __half2 h1 = *reinterpret_cast<__half2*>(&v.y);
    __half2 h2 = *reinterpret_cast<__half2*>(&v.z);
    __half2 h3 = *reinterpret_cast<__half2*>(&v.w);
    float2 f0 = __half22float2(h0);
    float2 f1 = __half22float2(h1);
    float2 f2 = __half22float2(h2);
    float2 f3 = __half22float2(h3);
    a[0] += f0.x; a[1] += f0.y; a[2] += f1.x; a[3] += f1.y;
    a[4] += f2.x; a[5] += f2.y; a[6] += f3.x; a[7] += f3.y;
}

template <int F, int MODE, bool OUTH>
__global__ void k_agg_h(const __half* __restrict__ tmp, const float* __restrict__ bias,
                        void* __restrict__ outv, int n) {
    constexpr int G = F / 8;
    int t = blockIdx.x * blockDim.x + threadIdx.x;
    int node = t / G;
    int lane = t % G;
    if (node >= n) return;

    const uint4* t4 = (const uint4*)tmp;
    size_t base = (size_t)node * G + lane;

    float acc[8] = {0, 0, 0, 0, 0, 0, 0, 0};
    add8(acc, __ldg(&t4[base]));  // self-loop term

    int start = g_rowstart[node];
    int c = g_cnt[node];
    int j = 0;
    for (; j + 4 <= c; j += 4) {
        int s0 = __ldg(&g_csrc[start + j + 0]);
        int s1 = __ldg(&g_csrc[start + j + 1]);
        int s2 = __ldg(&g_csrc[start + j + 2]);
        int s3 = __ldg(&g_csrc[start + j + 3]);
        uint4 v0 = __ldg(&t4[(size_t)s0 * G + lane]);
        uint4 v1 = __ldg(&t4[(size_t)s1 * G + lane]);
        uint4 v2 = __ldg(&t4[(size_t)s2 * G + lane]);
        uint4 v3 = __ldg(&t4[(size_t)s3 * G + lane]);
        add8(acc, v0); add8(acc, v1); add8(acc, v2); add8(acc, v3);
    }
    for (; j < c; j++) {
        int s = __ldg(&g_csrc[start + j]);
        add8(acc, __ldg(&t4[(size_t)s * G + lane]));
    }

    float di = g_dinv[node];
    float r[8];
    if (MODE == AGG_PRE) {
        #pragma unroll
        for (int i = 0; i < 8; i++) r[i] = di * acc[i];
    } else {
        #pragma unroll
        for (int i = 0; i < 8; i++) {
            float b = __ldg(&bias[lane * 8 + i]);
            r[i] = fmaxf(fmaf(di, acc[i], b), 0.0f);
            if (MODE == AGG_RELU_DINV) r[i] *= di;
        }
    }

    if (OUTH) {
        uint4 o;
        __half2 p0 = __floats2half2_rn(r[0], r[1]);
        __half2 p1 = __floats2half2_rn(r[2], r[3]);
        __half2 p2 = __floats2half2_rn(r[4], r[5]);
        __half2 p3 = __floats2half2_rn(r[6], r[7]);
        o.x = *reinterpret_cast<unsigned*>(&p0);
        o.y = *reinterpret_cast<unsigned*>(&p1);
        o.z = *reinterpret_cast<unsigned*>(&p2);
        o.w = *reinterpret_cast<unsigned*>(&p3);
        ((uint4*)outv)[base] = o;
    } else {
        float4* out = (float4*)outv;
        size_t fbase = (size_t)node * (F / 4) + lane * 2;
        out[fbase + 0] = make_float4(r[0], r[1], r[2], r[3]);
        out[fbase + 1] = make_float4(r[4], r[5], r[6], r[7]);
    }
}

// Final layer: aggregate Fout=2 (fp32) and fuse log_softmax, write to d_out
__global__ void k_agg_final(const float* __restrict__ tmp, const float* __restrict__ bias,
                            float* __restrict__ out, int n) {
    int node = blockIdx.x * blockDim.x + threadIdx.x;
    if (node >= n) return;
    const float2* t2 = (const float2*)tmp;
    float2 acc = __ldg(&t2[node]);  // self
    int start = g_rowstart[node];
    int c = g_cnt[node];
    int j = 0;
    for (; j + 4 <= c; j += 4) {
        int s0 = __ldg(&g_csrc[start + j + 0]);
        int s1 = __ldg(&g_csrc[start + j + 1]);
        int s2 = __ldg(&g_csrc[start + j + 2]);
        int s3 = __ldg(&g_csrc[start + j + 3]);
        float2 v0 = __ldg(&t2[s0]);
        float2 v1 = __ldg(&t2[s1]);
        float2 v2 = __ldg(&t2[s2]);
        float2 v3 = __ldg(&t2[s3]);
        acc.x += (v0.x + v1.x) + (v2.x + v3.x);
        acc.y += (v0.y + v1.y) + (v2.y + v3.y);
    }
    for (; j < c; j++) {
        float2 v = __ldg(&t2[__ldg(&g_csrc[start + j])]);
        acc.x += v.x; acc.y += v.y;
    }
    float di = g_dinv[node];
    float z0 = fmaf(di, acc.x, bias[0]);
    float z1 = fmaf(di, acc.y, bias[1]);
    float m = fmaxf(z0, z1);
    float l = m + logf(expf(z0 - m) + expf(z1 - m));
    out[(size_t)node * 2 + 0] = z0 - l;
    out[(size_t)node * 2 + 1] = z1 - l;
}

// ---------------- launch -------------------------------------------------------
extern "C" void kernel_launch(void* const* d_in, const int* in_sizes, int n_in,
                              void* d_out, int out_size) {
    const float* x  = (const float*)d_in[0];
    const void*  ei = d_in[1];
    const float* W1 = (const float*)d_in[2];  const float* b1 = (const float*)d_in[3];
    const float* W2 = (const float*)d_in[4];  const float* b2 = (const float*)d_in[5];
    const float* W3 = (const float*)d_in[6];  const float* b3 = (const float*)d_in[7];
    const float* W4 = (const float*)d_in[8];  const float* b4 = (const float*)d_in[9];
    const float* W5 = (const float*)d_in[10]; const float* b5 = (const float*)d_in[11];

    int n = in_sizes[0] / 256;  // 100000
    int e = in_sizes[1] / 2;    // 3200000

    void* bufA = nullptr;   // g_tmp
    void* bufB = nullptr;   // g_h
    cudaGetSymbolAddress(&bufA, g_tmp);
    cudaGetSymbolAddress(&bufB, g_h);

    int nb_n = (n + 255) / 256;   // 391
    int nb_e = (e + 255) / 256;

    // graph preprocessing — 5 launches
    k_init<<<nb_n, 256>>>((const int*)ei, n);
    k_count<<<nb_e, 256>>>(ei, e, n);
    k_bsum<<<nb_n, 256>>>(n);
    k_final<<<nb_n, 256>>>(n, nb_n);
    k_scatter<<<nb_e, 256>>>(ei, e, n);

    int tc_blocks = (n + 31) / 32;      // 3125
    int agg64_blocks = (int)(((size_t)n * 8 + 255) / 256);
    int agg16_blocks = (int)(((size_t)n * 2 + 255) / 256);

    // Layer 1: 256 -> 64 (tf32 TC; fp16 gather buffers)
    k_gemm_tc<256, 64, EPI_DINV, true><<<tc_blocks, 128>>>(x, W1, bufA, nullptr, n);
    k_agg_h<64, AGG_RELU_DINV, true><<<agg64_blocks, 256>>>((const __half*)bufA, b1, bufB, n);
    // Layer 2: 64 -> 128 (aggregate-FIRST at F=64 fp16, then tf32 TC GEMM w/ bias+relu)
    k_agg_h<64, AGG_PRE, false><<<agg64_blocks, 256>>>((const __half*)bufB, nullptr, bufA, n);
    k_gemm_tc<64, 128, EPI_BIAS_RELU, false><<<tc_blocks, 128>>>((const float*)bufA, W2, bufB, b2, n);
    // Layer 3: 128 -> 64 (tf32 TC)
    k_gemm_tc<128, 64, EPI_DINV, true><<<tc_blocks, 128>>>((const float*)bufB, W3, bufA, nullptr, n);
    k_agg_h<64, AGG_RELU, false><<<agg64_blocks, 256>>>((const __half*)bufA, b3, bufB, n);
    // Layer 4: 64 -> 16 (scalar f32x2)
    k_gemm<64, 16, EPI_DINV, true><<<tc_blocks, 256>>>((const float*)bufB, W4, bufA, nullptr, n);
    k_agg_h<16, AGG_RELU, false><<<agg16_blocks, 256>>>((const __half*)bufA, b4, bufB, n);
    // Layer 5: 16 -> 2, fp32 throughout, fused log_softmax
    k_gemm5<<<nb_n, 256>>>((const float*)bufB, W5, (float*)bufA, n);
    k_agg_final<<<nb_n, 256>>>((const float*)bufA, b5, (float*)d_out, n);
}

// round 8
// speedup vs baseline: 2.0833x; 1.0130x over previous
#include <cuda_runtime.h>
#include <cuda_fp16.h>
#include <mma.h>
#include <math.h>

using namespace nvcuda;

// Problem constants (fixed by the dataset)
#define N_MAX 100000
#define E_MAX 3200000
#define FMAX  128

// ---------------- device scratch ----------------------------------------------
__device__ float g_dinv[N_MAX];
__device__ int   g_cnt[N_MAX];
__device__ int   g_rowstart[N_MAX];
__device__ int   g_cursor[N_MAX];
__device__ int   g_csrc[E_MAX];
__device__ float g_tmp[(size_t)N_MAX * FMAX];   // generic buffer A
__device__ float g_h[(size_t)N_MAX * FMAX];     // generic buffer B
__device__ int   g_is64;
__device__ int   g_bsum[512];

// Epilogue modes
#define EPI_DINV      0
#define EPI_BIAS_RELU 1

#define AGG_RELU      0
#define AGG_RELU_DINV 1
#define AGG_PRE       2

// ---------------- graph preprocessing ----------------------------------------

__global__ void k_init(const int* __restrict__ w, int n) {
    int i = blockIdx.x * blockDim.x + threadIdx.x;
    if (i < n) g_cnt[i] = 0;
    if (blockIdx.x == 0 && threadIdx.x == 0) {
        int z = 0;
        #pragma unroll
        for (int k = 0; k < 64; k++) z |= w[2 * k + 1];
        g_is64 = (z == 0) ? 1 : 0;
    }
}

__global__ void k_count(const void* __restrict__ ei, int e, int n) {
    int t = blockIdx.x * blockDim.x + threadIdx.x;
    if (t >= e) return;
    int d;
    if (g_is64) d = (int)((const long long*)ei)[(size_t)e + t];
    else        d = ((const int*)ei)[e + t];
    if ((unsigned)d < (unsigned)n) atomicAdd(&g_cnt[d], 1);
}

__global__ void k_bsum(int n) {
    int i = blockIdx.x * 256 + threadIdx.x;
    int v = (i < n) ? g_cnt[i] : 0;
    #pragma unroll
    for (int o = 16; o; o >>= 1) v += __shfl_down_sync(0xFFFFFFFFu, v, o);
    __shared__ int ws[8];
    if ((threadIdx.x & 31) == 0) ws[threadIdx.x >> 5] = v;
    __syncthreads();
    if (threadIdx.x == 0) {
        int s = 0;
        #pragma unroll
        for (int j = 0; j < 8; j++) s += ws[j];
        g_bsum[blockIdx.x] = s;
    }
}

__global__ void k_final(int n, int nb) {
    __shared__ int s_off;
    {
        int p = 0;
        for (int i = threadIdx.x; i < blockIdx.x; i += 256) p += g_bsum[i];
        #pragma unroll
        for (int o = 16; o; o >>= 1) p += __shfl_down_sync(0xFFFFFFFFu, p, o);
        __shared__ int ws2[8];
        if ((threadIdx.x & 31) == 0) ws2[threadIdx.x >> 5] = p;
        __syncthreads();
        if (threadIdx.x == 0) {
            int s = 0;
            #pragma unroll
            for (int j = 0; j < 8; j++) s += ws2[j];
            s_off = s;
        }
    }
    int i = blockIdx.x * 256 + threadIdx.x;
    int v = (i < n) ? g_cnt[i] : 0;
    int lane = threadIdx.x & 31, wid = threadIdx.x >> 5;
    int x = v;
    #pragma unroll
    for (int o = 1; o < 32; o <<= 1) {
        int y = __shfl_up_sync(0xFFFFFFFFu, x, o);
        if (lane >= o) x += y;
    }
    __shared__ int ws[8];
    if (lane == 31) ws[wid] = x;
    __syncthreads();
    if (threadIdx.x < 8) {
        int y = ws[threadIdx.x];
        int z = y;
        #pragma unroll
        for (int o = 1; o < 8; o <<= 1) {
            int t2 = __shfl_up_sync(0xFFu, z, o);
            if (threadIdx.x >= o) z += t2;
        }
        ws[threadIdx.x] = z - y;
    }
    __syncthreads();
    if (i < n) {
        int excl = (x - v) + ws[wid] + s_off;
        g_rowstart[i] = excl;
        g_cursor[i]   = excl;
        g_dinv[i]     = rsqrtf((float)(v + 1));
    }
}

__global__ void k_scatter(const void* __restrict__ ei, int e, int n) {
    int t = blockIdx.x * blockDim.x + threadIdx.x;
    if (t >= e) return;
    int s, d;
    if (g_is64) {
        const long long* p = (const long long*)ei;
        s = (int)p[t];
        d = (int)p[(size_t)e + t];
    } else {
        const int* p = (const int*)ei;
        s = p[t];
        d = p[e + t];
    }
    if ((unsigned)s >= (unsigned)n || (unsigned)d >= (unsigned)n) return;
    int pos = atomicAdd(&g_cursor[d], 1);
    g_csrc[pos] = s;
}

// ---------------- tf32 tensor-core GEMM ----------------------------------------
// 64 rows/block, 128 threads (4 warps). Warp w: col tiles {w, w+4,...} x 4 row tiles.
// Staging + epilogue share one smem buffer (epilogue runs after the final sync).
template <int FIN, int FOUT, int EPI, bool OUTH>
__global__ void k_gemm_tc(const float* __restrict__ A, const float* __restrict__ W,
                          void* __restrict__ outv, const float* __restrict__ bias, int n) {
    constexpr int ROWS = 64;
    constexpr int RT = ROWS / 16;                 // 4 row tiles
    constexpr int KC = (FOUT >= 128) ? 32 : 64;   // k-chunk (smaller for wide FOUT)
    constexpr int NCH = FIN / KC;
    constexpr int SA_LD = KC + 8;
    constexpr int SW_LD = FOUT + 4;
    constexpr int CT = FOUT / 16;
    constexpr int CPW = CT / 4;                   // col tiles per warp

    constexpr int STAGE_FL = ROWS * SA_LD + KC * SW_LD;
    constexpr int EPI_FL   = ROWS * FOUT;
    constexpr int SMEM_FL  = (STAGE_FL > EPI_FL) ? STAGE_FL : EPI_FL;
    __shared__ __align__(16) float smem_buf[SMEM_FL];
    static_assert(SMEM_FL * 4 <= 48 * 1024, "static smem limit");

    float* sA = smem_buf;
    float* sW = smem_buf + ROWS * SA_LD;

    int row0 = blockIdx.x * ROWS;
    int t = threadIdx.x;
    int w = t >> 5;

    wmma::fragment<wmma::accumulator, 16, 16, 8, float> acc[RT][CPW];
    #pragma unroll
    for (int r = 0; r < RT; r++)
        #pragma unroll
        for (int j = 0; j < CPW; j++) wmma::fill_fragment(acc[r][j], 0.0f);

    for (int kc = 0; kc < NCH; kc++) {
        // stage A chunk: ROWS x KC (tf32-rounded)
        #pragma unroll
        for (int it = 0; it < ROWS * KC / 4 / 128; it++) {
            int idx = t + it * 128;
            int r = idx / (KC / 4), c4 = idx % (KC / 4);
            int grow = row0 + r;
            float4 a = (grow < n) ? __ldg((const float4*)(A + (size_t)grow * FIN + kc * KC + c4 * 4))
                                  : make_float4(0.f, 0.f, 0.f, 0.f);
            float* d = &sA[r * SA_LD + c4 * 4];
            d[0] = wmma::__float_to_tf32(a.x);
            d[1] = wmma::__float_to_tf32(a.y);
            d[2] = wmma::__float_to_tf32(a.z);
            d[3] = wmma::__float_to_tf32(a.w);
        }
        // stage W chunk: KC k-rows x FOUT cols
        #pragma unroll
        for (int it = 0; it < KC * FOUT / 4 / 128; it++) {
            int idx = t + it * 128;
            int k = idx / (FOUT / 4), c4 = idx % (FOUT / 4);
            float4 v = __ldg((const float4*)(W + (size_t)(kc * KC + k) * FOUT + c4 * 4));
            float* d = &sW[k * SW_LD + c4 * 4];
            d[0] = wmma::__float_to_tf32(v.x);
            d[1] = wmma::__float_to_tf32(v.y);
            d[2] = wmma::__float_to_tf32(v.z);
            d[3] = wmma::__float_to_tf32(v.w);
        }
        __syncthreads();

        #pragma unroll
        for (int ks = 0; ks < KC / 8; ks++) {
            wmma::fragment<wmma::matrix_a, 16, 16, 8, wmma::precision::tf32, wmma::row_major> af[RT];
            #pragma unroll
            for (int r = 0; r < RT; r++)
                wmma::load_matrix_sync(af[r], &sA[r * 16 * SA_LD + ks * 8], SA_LD);
            #pragma unroll
            for (int j = 0; j < CPW; j++) {
                wmma::fragment<wmma::matrix_b, 16, 16, 8, wmma::precision::tf32, wmma::row_major> b;
                wmma::load_matrix_sync(b, &sW[ks * 8 * SW_LD + (w + j * 4) * 16], SW_LD);
                #pragma unroll
                for (int r = 0; r < RT; r++)
                    wmma::mma_sync(acc[r][j], af[r], b, acc[r][j]);
            }
        }
        __syncthreads();
    }

    // epilogue: frags -> smem (whole buffer reused) -> global
    float* sEp = smem_buf;
    #pragma unroll
    for (int r = 0; r < RT; r++)
        #pragma unroll
        for (int j = 0; j < CPW; j++)
            wmma::store_matrix_sync(&sEp[r * 16 * FOUT + (w + j * 4) * 16], acc[r][j],
                                    FOUT, wmma::mem_row_major);
    __syncthreads();

    #pragma unroll
    for (int it = 0; it < ROWS * FOUT / 4 / 128; it++) {
        int idx = t + it * 128;
        int r = idx / (FOUT / 4), c4 = idx % (FOUT / 4);
        int grow = row0 + r;
        if (grow >= n) continue;
        float4 v = *(const float4*)&sEp[r * FOUT + c4 * 4];
        if (EPI == EPI_DINV) {
            float di = g_dinv[grow];
            v.x *= di; v.y *= di; v.z *= di; v.w *= di;
        } else {
            const float4 bb = __ldg((const float4*)(bias + c4 * 4));
            v.x = fmaxf(v.x + bb.x, 0.f);
            v.y = fmaxf(v.y + bb.y, 0.f);
            v.z = fmaxf(v.z + bb.z, 0.f);
            v.w = fmaxf(v.w + bb.w, 0.f);
        }
        if (OUTH) {
            __half2 p0 = __floats2half2_rn(v.x, v.y);
            __half2 p1 = __floats2half2_rn(v.z, v.w);
            uint2 o;
            o.x = *reinterpret_cast<unsigned*>(&p0);
            o.y = *reinterpret_cast<unsigned*>(&p1);
            *(uint2*)((__half*)outv + (size_t)grow * FOUT + c4 * 4) = o;
        } else {
            *(float4*)((float*)outv + (size_t)grow * FOUT + c4 * 4) = v;
        }
    }
}

// ---------------- scalar GEMM (layer 4: 64 -> 16) -------------------------------
template <int FIN, int FOUT, int EPI, bool OUTH>
__global__ void k_gemm(const float* __restrict__ A, const float* __restrict__ W,
                       void* __restrict__ outv, const float* __restrict__ bias, int n) {
    constexpr int ROWS = 32;
    constexpr int G = 256 / FOUT;
    constexpr int R = ROWS / G;
    constexpr int P = R / 2;
    constexpr int STRIDE = 2 * FIN + 2;
    __shared__ __align__(16) float sP[(ROWS / 2) * STRIDE];

    int row0 = blockIdx.x * ROWS;
    {
        int lane = threadIdx.x & 31, w = threadIdx.x >> 5;
        int grow = row0 + lane;
        float* dst = &sP[(lane >> 1) * STRIDE + (lane & 1)];
        const float4* src = (const float4*)(A + (size_t)grow * FIN);
        for (int k4 = w; k4 < FIN / 4; k4 += 8) {
            float4 a = (grow < n) ? __ldg(&src[k4]) : make_float4(0.f, 0.f, 0.f, 0.f);
            dst[2 * (4 * k4 + 0)] = a.x;
            dst[2 * (4 * k4 + 1)] = a.y;
            dst[2 * (4 * k4 + 2)] = a.z;
            dst[2 * (4 * k4 + 3)] = a.w;
        }
    }
    __syncthreads();

    int c  = threadIdx.x % FOUT;
    int rg = threadIdx.x / FOUT;

    unsigned long long acc[P];
    #pragma unroll
    for (int q = 0; q < P; q++) acc[q] = 0ULL;
    const float* base = &sP[(rg * P) * STRIDE];

    #pragma unroll 4
    for (int k = 0; k < FIN; k++) {
        float w = __ldg(&W[k * FOUT + c]);
        unsigned long long w2;
        asm("mov.b64 %0, {%1, %1};" : "=l"(w2) : "f"(w));
        #pragma unroll
        for (int q = 0; q < P; q++) {
            unsigned long long a = *(const unsigned long long*)&base[q * STRIDE + 2 * k];
            asm("fma.rn.f32x2 %0, %1, %2, %0;" : "+l"(acc[q]) : "l"(a), "l"(w2));
        }
    }

    float bc = (EPI == EPI_BIAS_RELU) ? __ldg(&bias[c]) : 0.0f;
    #pragma unroll
    for (int q = 0; q < P; q++) {
        float lo, hi;
        asm("mov.b64 {%0, %1}, %2;" : "=f"(lo), "=f"(hi) : "l"(acc[q]));
        int r0 = row0 + rg * R + 2 * q;
        float v0, v1;
        if (EPI == EPI_DINV) {
            v0 = lo * ((r0 < n) ? g_dinv[r0] : 0.f);
            v1 = hi * ((r0 + 1 < n) ? g_dinv[r0 + 1] : 0.f);
        } else {
            v0 = fmaxf(lo + bc, 0.0f);
            v1 = fmaxf(hi + bc, 0.0f);
        }
        if (OUTH) {
            __half* out = (__half*)outv;
            if (r0 < n)     out[(size_t)r0 * FOUT + c]       = __float2half_rn(v0);
            if (r0 + 1 < n) out[(size_t)(r0 + 1) * FOUT + c] = __float2half_rn(v1);
        } else {
            float* out = (float*)outv;
            if (r0 < n)     out[(size_t)r0 * FOUT + c]       = v0;
            if (r0 + 1 < n) out[(size_t)(r0 + 1) * FOUT + c] = v1;
        }
    }
}

// Special GEMM for layer 5 (FIN=16, FOUT=2)
__global__ void k_gemm5(const float* __restrict__ A, const float* __restrict__ W,
                        float* __restrict__ out, int n) {
    __shared__ float sW[32];
    if (threadIdx.x < 32) sW[threadIdx.x] = W[threadIdx.x];
    __syncthreads();
    int row = blockIdx.x * blockDim.x + threadIdx.x;
    if (row >= n) return;
    const float4* a4 = (const float4*)(A + (size_t)row * 16);
    float acc0 = 0.0f, acc1 = 0.0f;
    #pragma unroll
    for (int q = 0; q < 4; q++) {
        float4 a = __ldg(&a4[q]);
        acc0 = fmaf(a.x, sW[(4*q+0)*2+0], acc0);
        acc1 = fmaf(a.x, sW[(4*q+0)*2+1], acc1);
        acc0 = fmaf(a.y, sW[(4*q+1)*2+0], acc0);
        acc1 = fmaf(a.y, sW[(4*q+1)*2+1], acc1);
        acc0 = fmaf(a.z, sW[(4*q+2)*2+0], acc0);
        acc1 = fmaf(a.z, sW[(4*q+2)*2+1], acc1);
        acc0 = fmaf(a.w, sW[(4*q+3)*2+0], acc0);
        acc1 = fmaf(a.w, sW[(4*q+3)*2+1], acc1);
    }
    float di = g_dinv[row];
    out[(size_t)row * 2 + 0] = acc0 * di;
    out[(size_t)row * 2 + 1] = acc1 * di;
}

// ---------------- fp16 gather aggregation (half2 accumulation) ------------------
template <int F, int MODE, bool OUTH>
__global__ void k_agg_h(const __half* __restrict__ tmp, const float* __restrict__ bias,
                        void* __restrict__ outv, int n) {
    constexpr int G = F / 8;
    int t = blockIdx.x * blockDim.x + threadIdx.x;
    int node = t / G;
    int lane = t % G;
    if (node >= n) return;

    const uint4* t4 = (const uint4*)tmp;
    size_t base = (size_t)node * G + lane;

    // self-loop term initializes the half2 accumulators
    uint4 sv = __ldg(&t4[base]);
    __half2 a0 = *reinterpret_cast<__half2*>(&sv.x);
    __half2 a1 = *reinterpret_cast<__half2*>(&sv.y);
    __half2 a2 = *reinterpret_cast<__half2*>(&sv.z);
    __half2 a3 = *reinterpret_cast<__half2*>(&sv.w);

    int start = g_rowstart[node];
    int c = g_cnt[node];
    int j = 0;
    for (; j + 4 <= c; j += 4) {
        int s0 = __ldg(&g_csrc[start + j + 0]);
        int s1 = __ldg(&g_csrc[start + j + 1]);
        int s2 = __ldg(&g_csrc[start + j + 2]);
        int s3 = __ldg(&g_csrc[start + j + 3]);
        uint4 v0 = __ldg(&t4[(size_t)s0 * G + lane]);
        uint4 v1 = __ldg(&t4[(size_t)s1 * G + lane]);
        uint4 v2 = __ldg(&t4[(size_t)s2 * G + lane]);
        uint4 v3 = __ldg(&t4[(size_t)s3 * G + lane]);
        a0 = __hadd2(a0, __hadd2(*reinterpret_cast<__half2*>(&v0.x),
                                 *reinterpret_cast<__half2*>(&v1.x)));
        a1 = __hadd2(a1, __hadd2(*reinterpret_cast<__half2*>(&v0.y),
                                 *reinterpret_cast<__half2*>(&v1.y)));
        a2 = __hadd2(a2, __hadd2(*reinterpret_cast<__half2*>(&v0.z),
                                 *reinterpret_cast<__half2*>(&v1.z)));
        a3 = __hadd2(a3, __hadd2(*reinterpret_cast<__half2*>(&v0.w),
                                 *reinterpret_cast<__half2*>(&v1.w)));
        a0 = __hadd2(a0, __hadd2(*reinterpret_cast<__half2*>(&v2.x),
                                 *reinterpret_cast<__half2*>(&v3.x)));
        a1 = __hadd2(a1, __hadd2(*reinterpret_cast<__half2*>(&v2.y),
                                 *reinterpret_cast<__half2*>(&v3.y)));
        a2 = __hadd2(a2, __hadd2(*reinterpret_cast<__half2*>(&v2.z),
                                 *reinterpret_cast<__half2*>(&v3.z)));
        a3 = __hadd2(a3, __hadd2(*reinterpret_cast<__half2*>(&v2.w),
                                 *reinterpret_cast<__half2*>(&v3.w)));
    }
    for (; j < c; j++) {
        int s = __ldg(&g_csrc[start + j]);
        uint4 v = __ldg(&t4[(size_t)s * G + lane]);
        a0 = __hadd2(a0, *reinterpret_cast<__half2*>(&v.x));
        a1 = __hadd2(a1, *reinterpret_cast<__half2*>(&v.y));
        a2 = __hadd2(a2, *reinterpret_cast<__half2*>(&v.z));
        a3 = __hadd2(a3, *reinterpret_cast<__half2*>(&v.w));
    }

    float2 f0 = __half22float2(a0);
    float2 f1 = __half22float2(a1);
    float2 f2 = __half22float2(a2);
    float2 f3 = __half22float2(a3);
    float acc[8] = {f0.x, f0.y, f1.x, f1.y, f2.x, f2.y, f3.x, f3.y};

    float di = g_dinv[node];
    float r[8];
    if (MODE == AGG_PRE) {
        #pragma unroll
        for (int i = 0; i < 8; i++) r[i] = di * acc[i];
    } else {
        #pragma unroll
        for (int i = 0; i < 8; i++) {
            float b = __ldg(&bias[lane * 8 + i]);
            r[i] = fmaxf(fmaf(di, acc[i], b), 0.0f);
            if (MODE == AGG_RELU_DINV) r[i] *= di;
        }
    }

    if (OUTH) {
        uint4 o;
        __half2 p0 = __floats2half2_rn(r[0], r[1]);
        __half2 p1 = __floats2half2_rn(r[2], r[3]);
        __half2 p2 = __floats2half2_rn(r[4], r[5]);
        __half2 p3 = __floats2half2_rn(r[6], r[7]);
        o.x = *reinterpret_cast<unsigned*>(&p0);
        o.y = *reinterpret_cast<unsigned*>(&p1);
        o.z = *reinterpret_cast<unsigned*>(&p2);
        o.w = *reinterpret_cast<unsigned*>(&p3);
        ((uint4*)outv)[base] = o;
    } else {
        float4* out = (float4*)outv;
        size_t fbase = (size_t)node * (F / 4) + lane * 2;
        out[fbase + 0] = make_float4(r[0], r[1], r[2], r[3]);
        out[fbase + 1] = make_float4(r[4], r[5], r[6], r[7]);
    }
}

// Final layer: aggregate Fout=2 (fp32) and fuse log_softmax, write to d_out
__global__ void k_agg_final(const float* __restrict__ tmp, const float* __restrict__ bias,
                            float* __restrict__ out, int n) {
    int node = blockIdx.x * blockDim.x + threadIdx.x;
    if (node >= n) return;
    const float2* t2 = (const float2*)tmp;
    float2 acc = __ldg(&t2[node]);
    int start = g_rowstart[node];
    int c = g_cnt[node];
    int j = 0;
    for (; j + 4 <= c; j += 4) {
        int s0 = __ldg(&g_csrc[start + j + 0]);
        int s1 = __ldg(&g_csrc[start + j + 1]);
        int s2 = __ldg(&g_csrc[start + j + 2]);
        int s3 = __ldg(&g_csrc[start + j + 3]);
        float2 v0 = __ldg(&t2[s0]);
        float2 v1 = __ldg(&t2[s1]);
        float2 v2 = __ldg(&t2[s2]);
        float2 v3 = __ldg(&t2[s3]);
        acc.x += (v0.x + v1.x) + (v2.x + v3.x);
        acc.y += (v0.y + v1.y) + (v2.y + v3.y);
    }
    for (; j < c; j++) {
        float2 v = __ldg(&t2[__ldg(&g_csrc[start + j])]);
        acc.x += v.x; acc.y += v.y;
    }
    float di = g_dinv[node];
    float z0 = fmaf(di, acc.x, bias[0]);
    float z1 = fmaf(di, acc.y, bias[1]);
    float m = fmaxf(z0, z1);
    float l = m + logf(expf(z0 - m) + expf(z1 - m));
    out[(size_t)node * 2 + 0] = z0 - l;
    out[(size_t)node * 2 + 1] = z1 - l;
}

// ---------------- launch -------------------------------------------------------
extern "C" void kernel_launch(void* const* d_in, const int* in_sizes, int n_in,
                              void* d_out, int out_size) {
    const float* x  = (const float*)d_in[0];
    const void*  ei = d_in[1];
    const float* W1 = (const float*)d_in[2];  const float* b1 = (const float*)d_in[3];
    const float* W2 = (const float*)d_in[4];  const float* b2 = (const float*)d_in[5];
    const float* W3 = (const float*)d_in[6];  const float* b3 = (const float*)d_in[7];
    const float* W4 = (const float*)d_in[8];  const float* b4 = (const float*)d_in[9];
    const float* W5 = (const float*)d_in[10]; const float* b5 = (const float*)d_in[11];

    int n = in_sizes[0] / 256;  // 100000
    int e = in_sizes[1] / 2;    // 3200000

    void* bufA = nullptr;
    void* bufB = nullptr;
    cudaGetSymbolAddress(&bufA, g_tmp);
    cudaGetSymbolAddress(&bufB, g_h);

    int nb_n = (n + 255) / 256;
    int nb_e = (e + 255) / 256;

    // graph preprocessing — 5 launches
    k_init<<<nb_n, 256>>>((const int*)ei, n);
    k_count<<<nb_e, 256>>>(ei, e, n);
    k_bsum<<<nb_n, 256>>>(n);
    k_final<<<nb_n, 256>>>(n, nb_n);
    k_scatter<<<nb_e, 256>>>(ei, e, n);

    int tc_blocks = (n + 63) / 64;      // 1563
    int sc_blocks = (n + 31) / 32;
    int agg64_blocks = (int)(((size_t)n * 8 + 255) / 256);
    int agg16_blocks = (int)(((size_t)n * 2 + 255) / 256);

    // Layer 1: 256 -> 64 (tf32 TC; fp16 gather buffers)
    k_gemm_tc<256, 64, EPI_DINV, true><<<tc_blocks, 128>>>(x, W1, bufA, nullptr, n);
    k_agg_h<64, AGG_RELU_DINV, true><<<agg64_blocks, 256>>>((const __half*)bufA, b1, bufB, n);
    // Layer 2: 64 -> 128 (aggregate-FIRST at F=64 fp16, then tf32 TC GEMM w/ bias+relu)
    k_agg_h<64, AGG_PRE, false><<<agg64_blocks, 256>>>((const __half*)bufB, nullptr, bufA, n);
    k_gemm_tc<64, 128, EPI_BIAS_RELU, false><<<tc_blocks, 128>>>((const float*)bufA, W2, bufB, b2, n);
    // Layer 3: 128 -> 64 (tf32 TC)
    k_gemm_tc<128, 64, EPI_DINV, true><<<tc_blocks, 128>>>((const float*)bufB, W3, bufA, nullptr, n);
    k_agg_h<64, AGG_RELU, false><<<agg64_blocks, 256>>>((const __half*)bufA, b3, bufB, n);
    // Layer 4: 64 -> 16 (scalar f32x2)
    k_gemm<64, 16, EPI_DINV, true><<<sc_blocks, 256>>>((const float*)bufB, W4, bufA, nullptr, n);
    k_agg_h<16, AGG_RELU, false><<<agg16_blocks, 256>>>((const __half*)bufA, b4, bufB, n);
    // Layer 5: 16 -> 2, fp32 throughout, fused log_softmax
    k_gemm5<<<nb_n, 256>>>((const float*)bufB, W5, (float*)bufA, n);
    k_agg_final<<<nb_n, 256>>>((const float*)bufA, b5, (float*)d_out, n);
}

// round 9
// speedup vs baseline: 2.1030x; 1.0094x over previous
#include <cuda_runtime.h>
#include <cuda_fp16.h>
#include <mma.h>
#include <math.h>

using namespace nvcuda;

// Problem constants (fixed by the dataset)
#define N_MAX 100000
#define E_MAX 3200000
#define FMAX  128

// ---------------- device scratch ----------------------------------------------
__device__ float g_dinv[N_MAX];
__device__ int   g_cnt[N_MAX];
__device__ int   g_rowstart[N_MAX];
__device__ int   g_cursor[N_MAX];
__device__ __align__(16) int g_csrc[E_MAX + 4 * N_MAX];  // 4-aligned row starts
__device__ float g_tmp[(size_t)N_MAX * FMAX];   // generic buffer A
__device__ float g_h[(size_t)N_MAX * FMAX];     // generic buffer B
__device__ int   g_is64;
__device__ int   g_ticket;
__device__ long long g_bstate[512];             // (sum<<32) | flag; 0=none,1=agg,2=prefix

// Epilogue modes
#define EPI_DINV      0
#define EPI_BIAS_RELU 1

#define AGG_RELU      0
#define AGG_RELU_DINV 1
#define AGG_PRE       2

// ---------------- graph preprocessing ----------------------------------------

__global__ void k_init(const int* __restrict__ w, int n) {
    int i = blockIdx.x * blockDim.x + threadIdx.x;
    if (i < n) g_cnt[i] = 0;
    if (i < 512) g_bstate[i] = 0;
    if (i == 0) {
        g_ticket = 0;
        int z = 0;
        #pragma unroll
        for (int k = 0; k < 64; k++) z |= w[2 * k + 1];
        g_is64 = (z == 0) ? 1 : 0;
    }
}

__global__ void k_count(const void* __restrict__ ei, int e, int n) {
    int t = blockIdx.x * blockDim.x + threadIdx.x;
    if (t >= e) return;
    int d;
    if (g_is64) d = (int)((const long long*)ei)[(size_t)e + t];
    else        d = ((const int*)ei)[e + t];
    if ((unsigned)d < (unsigned)n) atomicAdd(&g_cnt[d], 1);
}

// single-pass decoupled-lookback scan of padded counts; writes rowstart/cursor/dinv
__global__ void k_scan(int n) {
    __shared__ int s_bid;
    if (threadIdx.x == 0) s_bid = atomicAdd(&g_ticket, 1);
    __syncthreads();
    int bid = s_bid;

    int i = bid * 256 + threadIdx.x;
    int v = (i < n) ? g_cnt[i] : 0;
    int pv = (v + 3) & ~3;          // pad each row to multiple of 4 (int4 idx loads)

    // intra-block inclusive scan of pv
    int lane = threadIdx.x & 31, wid = threadIdx.x >> 5;
    int x = pv;
    #pragma unroll
    for (int o = 1; o < 32; o <<= 1) {
        int y = __shfl_up_sync(0xFFFFFFFFu, x, o);
        if (lane >= o) x += y;
    }
    __shared__ int ws[8];
    if (lane == 31) ws[wid] = x;
    __syncthreads();
    __shared__ int s_excl;
    if (threadIdx.x == 0) {
        int tot = 0;
        #pragma unroll
        for (int j = 0; j < 8; j++) tot += ws[j];
        // publish aggregate (or prefix for block 0)
        long long st = ((long long)tot << 32) | (bid == 0 ? 2LL : 1LL);
        atomicExch((unsigned long long*)&g_bstate[bid], (unsigned long long)st);
        int excl = 0;
        if (bid > 0) {
            int j = bid - 1;
            while (true) {
                long long s = (long long)atomicAdd((unsigned long long*)&g_bstate[j], 0ULL);
                int flag = (int)(s & 3);
                if (flag == 2) { excl += (int)(s >> 32); break; }
                if (flag == 1) { excl += (int)(s >> 32); j--; }
            }
            long long st2 = ((long long)(excl + tot) << 32) | 2LL;
            atomicExch((unsigned long long*)&g_bstate[bid], (unsigned long long)st2);
        }
        s_excl = excl;
    }
    // exclusive warp offsets
    __syncthreads();
    __shared__ int wo[8];
    if (threadIdx.x < 8) {
        int y = ws[threadIdx.x];
        int z = y;
        #pragma unroll
        for (int o = 1; o < 8; o <<= 1) {
            int t2 = __shfl_up_sync(0xFFu, z, o);
            if (threadIdx.x >= o) z += t2;
        }
        wo[threadIdx.x] = z - y;
    }
    __syncthreads();
    if (i < n) {
        int start = s_excl + wo[wid] + (x - pv);
        g_rowstart[i] = start;
        g_cursor[i]   = start;
        g_dinv[i]     = rsqrtf((float)(v + 1));
    }
}

__global__ void k_scatter(const void* __restrict__ ei, int e, int n) {
    int t = blockIdx.x * blockDim.x + threadIdx.x;
    if (t >= e) return;
    int s, d;
    if (g_is64) {
        const long long* p = (const long long*)ei;
        s = (int)p[t];
        d = (int)p[(size_t)e + t];
    } else {
        const int* p = (const int*)ei;
        s = p[t];
        d = p[e + t];
    }
    if ((unsigned)s >= (unsigned)n || (unsigned)d >= (unsigned)n) return;
    int pos = atomicAdd(&g_cursor[d], 1);
    g_csrc[pos] = s;
}

// ---------------- tf32 tensor-core GEMM ----------------------------------------
template <int FIN, int FOUT, int EPI, bool OUTH>
__global__ void k_gemm_tc(const float* __restrict__ A, const float* __restrict__ W,
                          void* __restrict__ outv, const float* __restrict__ bias, int n) {
    constexpr int ROWS = 64;
    constexpr int RT = ROWS / 16;
    constexpr int KC = (FOUT >= 128) ? 32 : 64;
    constexpr int NCH = FIN / KC;
    constexpr int SA_LD = KC + 8;
    constexpr int SW_LD = FOUT + 4;
    constexpr int CT = FOUT / 16;
    constexpr int CPW = CT / 4;

    constexpr int STAGE_FL = ROWS * SA_LD + KC * SW_LD;
    constexpr int EPI_FL   = ROWS * FOUT;
    constexpr int SMEM_FL  = (STAGE_FL > EPI_FL) ? STAGE_FL : EPI_FL;
    __shared__ __align__(16) float smem_buf[SMEM_FL];
    static_assert(SMEM_FL * 4 <= 48 * 1024, "static smem limit");

    float* sA = smem_buf;
    float* sW = smem_buf + ROWS * SA_LD;

    int row0 = blockIdx.x * ROWS;
    int t = threadIdx.x;
    int w = t >> 5;

    wmma::fragment<wmma::accumulator, 16, 16, 8, float> acc[RT][CPW];
    #pragma unroll
    for (int r = 0; r < RT; r++)
        #pragma unroll
        for (int j = 0; j < CPW; j++) wmma::fill_fragment(acc[r][j], 0.0f);

    for (int kc = 0; kc < NCH; kc++) {
        #pragma unroll
        for (int it = 0; it < ROWS * KC / 4 / 128; it++) {
            int idx = t + it * 128;
            int r = idx / (KC / 4), c4 = idx % (KC / 4);
            int grow = row0 + r;
            float4 a = (grow < n) ? __ldg((const float4*)(A + (size_t)grow * FIN + kc * KC + c4 * 4))
                                  : make_float4(0.f, 0.f, 0.f, 0.f);
            float* d = &sA[r * SA_LD + c4 * 4];
            d[0] = wmma::__float_to_tf32(a.x);
            d[1] = wmma::__float_to_tf32(a.y);
            d[2] = wmma::__float_to_tf32(a.z);
            d[3] = wmma::__float_to_tf32(a.w);
        }
        #pragma unroll
        for (int it = 0; it < KC * FOUT / 4 / 128; it++) {
            int idx = t + it * 128;
            int k = idx / (FOUT / 4), c4 = idx % (FOUT / 4);
            float4 v = __ldg((const float4*)(W + (size_t)(kc * KC + k) * FOUT + c4 * 4));
            float* d = &sW[k * SW_LD + c4 * 4];
            d[0] = wmma::__float_to_tf32(v.x);
            d[1] = wmma::__float_to_tf32(v.y);
            d[2] = wmma::__float_to_tf32(v.z);
            d[3] = wmma::__float_to_tf32(v.w);
        }
        __syncthreads();

        #pragma unroll
        for (int ks = 0; ks < KC / 8; ks++) {
            wmma::fragment<wmma::matrix_a, 16, 16, 8, wmma::precision::tf32, wmma::row_major> af[RT];
            #pragma unroll
            for (int r = 0; r < RT; r++)
                wmma::load_matrix_sync(af[r], &sA[r * 16 * SA_LD + ks * 8], SA_LD);
            #pragma unroll
            for (int j = 0; j < CPW; j++) {
                wmma::fragment<wmma::matrix_b, 16, 16, 8, wmma::precision::tf32, wmma::row_major> b;
                wmma::load_matrix_sync(b, &sW[ks * 8 * SW_LD + (w + j * 4) * 16], SW_LD);
                #pragma unroll
                for (int r = 0; r < RT; r++)
                    wmma::mma_sync(acc[r][j], af[r], b, acc[r][j]);
            }
        }
        __syncthreads();
    }

    float* sEp = smem_buf;
    #pragma unroll
    for (int r = 0; r < RT; r++)
        #pragma unroll
        for (int j = 0; j < CPW; j++)
            wmma::store_matrix_sync(&sEp[r * 16 * FOUT + (w + j * 4) * 16], acc[r][j],
                                    FOUT, wmma::mem_row_major);
    __syncthreads();

    #pragma unroll
    for (int it = 0; it < ROWS * FOUT / 4 / 128; it++) {
        int idx = t + it * 128;
        int r = idx / (FOUT / 4), c4 = idx % (FOUT / 4);
        int grow = row0 + r;
        if (grow >= n) continue;
        float4 v = *(const float4*)&sEp[r * FOUT + c4 * 4];
        if (EPI == EPI_DINV) {
            float di = g_dinv[grow];
            v.x *= di; v.y *= di; v.z *= di; v.w *= di;
        } else {
            const float4 bb = __ldg((const float4*)(bias + c4 * 4));
            v.x = fmaxf(v.x + bb.x, 0.f);
            v.y = fmaxf(v.y + bb.y, 0.f);
            v.z = fmaxf(v.z + bb.z, 0.f);
            v.w = fmaxf(v.w + bb.w, 0.f);
        }
        if (OUTH) {
            __half2 p0 = __floats2half2_rn(v.x, v.y);
            __half2 p1 = __floats2half2_rn(v.z, v.w);
            uint2 o;
            o.x = *reinterpret_cast<unsigned*>(&p0);
            o.y = *reinterpret_cast<unsigned*>(&p1);
            *(uint2*)((__half*)outv + (size_t)grow * FOUT + c4 * 4) = o;
        } else {
            *(float4*)((float*)outv + (size_t)grow * FOUT + c4 * 4) = v;
        }
    }
}

// ---------------- gather core (fp16 storage, half2 accumulate, int4 indices) ----
// Accumulates self + neighbors for (node, lane) into 4 half2 accumulators.
template <int G>
__device__ __forceinline__ void gather_accum(const uint4* __restrict__ t4, int node, int lane,
                                             __half2& a0, __half2& a1, __half2& a2, __half2& a3) {
    uint4 sv = __ldg(&t4[(size_t)node * G + lane]);
    a0 = *reinterpret_cast<__half2*>(&sv.x);
    a1 = *reinterpret_cast<__half2*>(&sv.y);
    a2 = *reinterpret_cast<__half2*>(&sv.z);
    a3 = *reinterpret_cast<__half2*>(&sv.w);

    int start = g_rowstart[node];
    int c = g_cnt[node];
    const int4* idx4 = (const int4*)(g_csrc + start);   // start is 4-aligned
    int j = 0;
    for (; j + 4 <= c; j += 4) {
        int4 s4 = __ldg(&idx4[j >> 2]);
        uint4 v0 = __ldg(&t4[(size_t)s4.x * G + lane]);
        uint4 v1 = __ldg(&t4[(size_t)s4.y * G + lane]);
        uint4 v2 = __ldg(&t4[(size_t)s4.z * G + lane]);
        uint4 v3 = __ldg(&t4[(size_t)s4.w * G + lane]);
        a0 = __hadd2(a0, __hadd2(*reinterpret_cast<__half2*>(&v0.x),
                                 *reinterpret_cast<__half2*>(&v1.x)));
        a1 = __hadd2(a1, __hadd2(*reinterpret_cast<__half2*>(&v0.y),
                                 *reinterpret_cast<__half2*>(&v1.y)));
        a2 = __hadd2(a2, __hadd2(*reinterpret_cast<__half2*>(&v0.z),
                                 *reinterpret_cast<__half2*>(&v1.z)));
        a3 = __hadd2(a3, __hadd2(*reinterpret_cast<__half2*>(&v0.w),
                                 *reinterpret_cast<__half2*>(&v1.w)));
        a0 = __hadd2(a0, __hadd2(*reinterpret_cast<__half2*>(&v2.x),
                                 *reinterpret_cast<__half2*>(&v3.x)));
        a1 = __hadd2(a1, __hadd2(*reinterpret_cast<__half2*>(&v2.y),
                                 *reinterpret_cast<__half2*>(&v3.y)));
        a2 = __hadd2(a2, __hadd2(*reinterpret_cast<__half2*>(&v2.z),
                                 *reinterpret_cast<__half2*>(&v3.z)));
        a3 = __hadd2(a3, __hadd2(*reinterpret_cast<__half2*>(&v2.w),
                                 *reinterpret_cast<__half2*>(&v3.w)));
    }
    for (; j < c; j++) {
        int s = __ldg(&g_csrc[start + j]);
        uint4 v = __ldg(&t4[(size_t)s * G + lane]);
        a0 = __hadd2(a0, *reinterpret_cast<__half2*>(&v.x));
        a1 = __hadd2(a1, *reinterpret_cast<__half2*>(&v.y));
        a2 = __hadd2(a2, *reinterpret_cast<__half2*>(&v.z));
        a3 = __hadd2(a3, *reinterpret_cast<__half2*>(&v.w));
    }
}

// generic aggregation kernel (F=64 variants)
template <int F, int MODE, bool OUTH>
__global__ void k_agg_h(const __half* __restrict__ tmp, const float* __restrict__ bias,
                        void* __restrict__ outv, int n) {
    constexpr int G = F / 8;
    int t = blockIdx.x * blockDim.x + threadIdx.x;
    int node = t / G;
    int lane = t % G;
    if (node >= n) return;

    __half2 a0, a1, a2, a3;
    gather_accum<G>((const uint4*)tmp, node, lane, a0, a1, a2, a3);

    float2 f0 = __half22float2(a0);
    float2 f1 = __half22float2(a1);
    float2 f2 = __half22float2(a2);
    float2 f3 = __half22float2(a3);
    float acc[8] = {f0.x, f0.y, f1.x, f1.y, f2.x, f2.y, f3.x, f3.y};

    float di = g_dinv[node];
    float r[8];
    if (MODE == AGG_PRE) {
        #pragma unroll
        for (int i = 0; i < 8; i++) r[i] = di * acc[i];
    } else {
        #pragma unroll
        for (int i = 0; i < 8; i++) {
            float b = __ldg(&bias[lane * 8 + i]);
            r[i] = fmaxf(fmaf(di, acc[i], b), 0.0f);
            if (MODE == AGG_RELU_DINV) r[i] *= di;
        }
    }

    size_t base = (size_t)node * G + lane;
    if (OUTH) {
        uint4 o;
        __half2 p0 = __floats2half2_rn(r[0], r[1]);
        __half2 p1 = __floats2half2_rn(r[2], r[3]);
        __half2 p2 = __floats2half2_rn(r[4], r[5]);
        __half2 p3 = __floats2half2_rn(r[6], r[7]);
        o.x = *reinterpret_cast<unsigned*>(&p0);
        o.y = *reinterpret_cast<unsigned*>(&p1);
        o.z = *reinterpret_cast<unsigned*>(&p2);
        o.w = *reinterpret_cast<unsigned*>(&p3);
        ((uint4*)outv)[base] = o;
    } else {
        float4* out = (float4*)outv;
        size_t fbase = (size_t)node * (F / 4) + lane * 2;
        out[fbase + 0] = make_float4(r[0], r[1], r[2], r[3]);
        out[fbase + 1] = make_float4(r[4], r[5], r[6], r[7]);
    }
}

// Fused layer-3 aggregation (F=64, bias+relu) + layer-4 GEMM (64 -> 16, * dinv), fp16 out.
__global__ void k_agg3_gemm4(const __half* __restrict__ tmp, const float* __restrict__ b3,
                             const float* __restrict__ W4, __half* __restrict__ out, int n) {
    constexpr int LD = 65;                  // conflict-free column for 32 node-rows
    __shared__ float sH[32 * LD];
    __shared__ float sW4[64 * 16];
    int t = threadIdx.x;

    #pragma unroll
    for (int i = t; i < 64 * 16; i += 256) sW4[i] = __ldg(&W4[i]);

    int nd = t >> 3;
    int lane = t & 7;
    int node = blockIdx.x * 32 + nd;
    int cnode = (node < n) ? node : (n - 1);   // clamp: keep all threads active

    __half2 a0, a1, a2, a3;
    gather_accum<8>((const uint4*)tmp, cnode, lane, a0, a1, a2, a3);

    float2 f0 = __half22float2(a0);
    float2 f1 = __half22float2(a1);
    float2 f2 = __half22float2(a2);
    float2 f3 = __half22float2(a3);
    float acc[8] = {f0.x, f0.y, f1.x, f1.y, f2.x, f2.y, f3.x, f3.y};

    float di = g_dinv[cnode];
    float* dst = &sH[nd * LD + lane * 8];
    #pragma unroll
    for (int i = 0; i < 8; i++) {
        float b = __ldg(&b3[lane * 8 + i]);
        dst[i] = fmaxf(fmaf(di, acc[i], b), 0.0f);
    }
    __syncthreads();

    // 64 -> 16 mini-GEMM: thread (nd, cp) computes cols 2cp, 2cp+1 for node nd
    int cp = t & 7;
    float z0 = 0.f, z1 = 0.f;
    const float* hrow = &sH[nd * LD];
    #pragma unroll 8
    for (int k = 0; k < 64; k++) {
        float h = hrow[k];
        float2 wv = *(const float2*)&sW4[k * 16 + cp * 2];
        z0 = fmaf(h, wv.x, z0);
        z1 = fmaf(h, wv.y, z1);
    }
    if (node < n) {
        float d2 = g_dinv[node];
        __half2 p = __floats2half2_rn(z0 * d2, z1 * d2);
        *(unsigned*)&out[(size_t)node * 16 + cp * 2] = *reinterpret_cast<unsigned*>(&p);
    }
}

// Fused layer-4 aggregation (F=16, bias+relu) + layer-5 GEMM (16 -> 2, * dinv), float2 out.
__global__ void k_agg4_gemm5(const __half* __restrict__ tmp, const float* __restrict__ b4,
                             const float* __restrict__ W5, float2* __restrict__ out, int n) {
    __shared__ float sW5[32];
    if (threadIdx.x < 32) sW5[threadIdx.x] = __ldg(&W5[threadIdx.x]);
    __syncthreads();

    int t = blockIdx.x * blockDim.x + threadIdx.x;
    int node = t >> 1;
    int lane = t & 1;
    int cnode = (node < n) ? node : (n - 1);   // clamp: keep shfl partners active

    __half2 a0, a1, a2, a3;
    gather_accum<2>((const uint4*)tmp, cnode, lane, a0, a1, a2, a3);

    float2 f0 = __half22float2(a0);
    float2 f1 = __half22float2(a1);
    float2 f2 = __half22float2(a2);
    float2 f3 = __half22float2(a3);
    float acc[8] = {f0.x, f0.y, f1.x, f1.y, f2.x, f2.y, f3.x, f3.y};

    float di = g_dinv[cnode];
    float z0 = 0.f, z1 = 0.f;
    #pragma unroll
    for (int i = 0; i < 8; i++) {
        float b = __ldg(&b4[lane * 8 + i]);
        float r = fmaxf(fmaf(di, acc[i], b), 0.0f);
        int k = lane * 8 + i;
        z0 = fmaf(r, sW5[k * 2 + 0], z0);
        z1 = fmaf(r, sW5[k * 2 + 1], z1);
    }
    z0 += __shfl_xor_sync(0xFFFFFFFFu, z0, 1);
    z1 += __shfl_xor_sync(0xFFFFFFFFu, z1, 1);
    if (lane == 0 && node < n) {
        out[node] = make_float2(z0 * di, z1 * di);
    }
}

// Final layer: aggregate Fout=2 (fp32) and fuse log_softmax, write to d_out
__global__ void k_agg_final(const float* __restrict__ tmp, const float* __restrict__ bias,
                            float* __restrict__ out, int n) {
    int node = blockIdx.x * blockDim.x + threadIdx.x;
    if (node >= n) return;
    const float2* t2 = (const float2*)tmp;
    float2 acc = __ldg(&t2[node]);
    int start = g_rowstart[node];
    int c = g_cnt[node];
    const int4* idx4 = (const int4*)(g_csrc + start);
    int j = 0;
    for (; j + 4 <= c; j += 4) {
        int4 s4 = __ldg(&idx4[j >> 2]);
        float2 v0 = __ldg(&t2[s4.x]);
        float2 v1 = __ldg(&t2[s4.y]);
        float2 v2 = __ldg(&t2[s4.z]);
        float2 v3 = __ldg(&t2[s4.w]);
        acc.x += (v0.x + v1.x) + (v2.x + v3.x);
        acc.y += (v0.y + v1.y) + (v2.y + v3.y);
    }
    for (; j < c; j++) {
        float2 v = __ldg(&t2[__ldg(&g_csrc[start + j])]);
        acc.x += v.x; acc.y += v.y;
    }
    float di = g_dinv[node];
    float z0 = fmaf(di, acc.x, bias[0]);
    float z1 = fmaf(di, acc.y, bias[1]);
    float m = fmaxf(z0, z1);
    float l = m + logf(expf(z0 - m) + expf(z1 - m));
    out[(size_t)node * 2 + 0] = z0 - l;
    out[(size_t)node * 2 + 1] = z1 - l;
}

// ---------------- launch -------------------------------------------------------
extern "C" void kernel_launch(void* const* d_in, const int* in_sizes, int n_in,
                              void* d_out, int out_size) {
    const float* x  = (const float*)d_in[0];
    const void*  ei = d_in[1];
    const float* W1 = (const float*)d_in[2];  const float* b1 = (const float*)d_in[3];
    const float* W2 = (const float*)d_in[4];  const float* b2 = (const float*)d_in[5];
    const float* W3 = (const float*)d_in[6];  const float* b3 = (const float*)d_in[7];
    const float* W4 = (const float*)d_in[8];  const float* b4 = (const float*)d_in[9];
    const float* W5 = (const float*)d_in[10]; const float* b5 = (const float*)d_in[11];

    int n = in_sizes[0] / 256;  // 100000
    int e = in_sizes[1] / 2;    // 3200000

    void* bufA = nullptr;
    void* bufB = nullptr;
    cudaGetSymbolAddress(&bufA, g_tmp);
    cudaGetSymbolAddress(&bufB, g_h);

    int nb_n = (n + 255) / 256;
    int nb_e = (e + 255) / 256;

    // graph preprocessing — 4 launches
    k_init<<<nb_n, 256>>>((const int*)ei, n);
    k_count<<<nb_e, 256>>>(ei, e, n);
    k_scan<<<nb_n, 256>>>(n);
    k_scatter<<<nb_e, 256>>>(ei, e, n);

    int tc_blocks = (n + 63) / 64;
    int agg64_blocks = (int)(((size_t)n * 8 + 255) / 256);
    int node32_blocks = (n + 31) / 32;
    int node128_blocks = (int)(((size_t)n * 2 + 255) / 256);

    // Layer 1: 256 -> 64 (tf32 TC; fp16 gather buffers)
    k_gemm_tc<256, 64, EPI_DINV, true><<<tc_blocks, 128>>>(x, W1, bufA, nullptr, n);
    k_agg_h<64, AGG_RELU_DINV, true><<<agg64_blocks, 256>>>((const __half*)bufA, b1, bufB, n);
    // Layer 2: 64 -> 128 (aggregate-FIRST at F=64 fp16, then tf32 TC GEMM w/ bias+relu)
    k_agg_h<64, AGG_PRE, false><<<agg64_blocks, 256>>>((const __half*)bufB, nullptr, bufA, n);
    k_gemm_tc<64, 128, EPI_BIAS_RELU, false><<<tc_blocks, 128>>>((const float*)bufA, W2, bufB, b2, n);
    // Layer 3: 128 -> 64 (tf32 TC, dinv, fp16 out)
    k_gemm_tc<128, 64, EPI_DINV, true><<<tc_blocks, 128>>>((const float*)bufB, W3, bufA, nullptr, n);
    // Fused: agg3(F=64, b3+relu) + gemm4(64->16, *dinv) -> fp16
    k_agg3_gemm4<<<node32_blocks, 256>>>((const __half*)bufA, b3, W4, (__half*)bufB, n);
    // Fused: agg4(F=16, b4+relu) + gemm5(16->2, *dinv) -> float2
    k_agg4_gemm5<<<node128_blocks, 256>>>((const __half*)bufB, b4, W5, (float2*)bufA, n);
    // Final aggregation + log_softmax
    k_agg_final<<<nb_n, 256>>>((const float*)bufA, b5, (float*)d_out, n);
}